// round 13
// baseline (speedup 1.0000x reference)
#include <cuda_runtime.h>
#include <cuda_bf16.h>
#include <cstdint>
#include <math.h>

#define MAXN 100000
#define MAXE 800000

// ---------------- device scratch ----------------
__device__ __nv_bfloat16 g_h0h[MAXN * 128], g_h0l[MAXN * 128];
__device__ float g_h0f[MAXN * 128];         // h0 tf32-rounded fp32 (for sv)
__device__ float g_h1f[MAXN * 128];         // h1 fp32 (attention out)
__device__ float g_qs[MAXN * 256];          // cols 0-127: q, 128-255: skip (fp32)
__device__ __nv_bfloat16 g_kb[MAXN * 128];  // k (bf16)
__device__ float g_v [MAXN * 128];          // v (fp32)
__device__ __nv_bfloat16 g_wth[9 * 128 * 128];
__device__ __nv_bfloat16 g_wtl[9 * 128 * 128];
__device__ float g_wtf[5 * 128 * 128];      // tf32 fp32: 0,1=sW|vW  2=uW1 3=uW2 4=uW3
__device__ float g_bcat[512];               // [qb|kb|sb|vb]
__device__ int   g_cnt[MAXN];
__device__ int   g_off[MAXN + 1];
__device__ int   g_bsum[256];
__device__ int   g_pos[MAXE];
__device__ int   g_esrc[MAXE];

// ---------------- side stream ----------------
static cudaStream_t g_s2;
static cudaEvent_t  g_ev_fork, g_ev_prep, g_ev_join;
namespace {
struct StreamInit {
    StreamInit() {
        cudaStreamCreateWithFlags(&g_s2, cudaStreamNonBlocking);
        cudaEventCreateWithFlags(&g_ev_fork, cudaEventDisableTiming);
        cudaEventCreateWithFlags(&g_ev_prep, cudaEventDisableTiming);
        cudaEventCreateWithFlags(&g_ev_join, cudaEventDisableTiming);
    }
};
StreamInit g_stream_init;
}

__device__ __forceinline__ uint32_t smem_u32(const void* p) {
    uint32_t a;
    asm("{ .reg .u64 t; cvta.to.shared.u64 t, %1; cvt.u32.u64 %0, t; }" : "=r"(a) : "l"(p));
    return a;
}
__device__ __forceinline__ uint32_t pack_bf16(float a, float b) {
    __nv_bfloat16 ha = __float2bfloat16(a);
    __nv_bfloat16 hb = __float2bfloat16(b);
    uint16_t ua = *(uint16_t*)&ha, ub = *(uint16_t*)&hb;
    return (uint32_t)ua | ((uint32_t)ub << 16);
}
__device__ __forceinline__ float to_tf32(float x) {
    float y; asm("cvt.rna.tf32.f32 %0, %1;" : "=f"(y) : "f"(x)); return y;
}
__device__ __forceinline__ void mma_bf16(float c[4], const uint32_t a[4], const uint32_t b[2]) {
    asm volatile(
        "mma.sync.aligned.m16n8k16.row.col.f32.bf16.bf16.f32 "
        "{%0,%1,%2,%3}, {%4,%5,%6,%7}, {%8,%9}, {%0,%1,%2,%3};"
        : "+f"(c[0]), "+f"(c[1]), "+f"(c[2]), "+f"(c[3])
        : "r"(a[0]), "r"(a[1]), "r"(a[2]), "r"(a[3]), "r"(b[0]), "r"(b[1]));
}
__device__ __forceinline__ void mma_tf32(float c[4], const uint32_t a[4], const uint32_t b[2]) {
    asm volatile(
        "mma.sync.aligned.m16n8k8.row.col.f32.tf32.tf32.f32 "
        "{%0,%1,%2,%3}, {%4,%5,%6,%7}, {%8,%9}, {%0,%1,%2,%3};"
        : "+f"(c[0]), "+f"(c[1]), "+f"(c[2]), "+f"(c[3])
        : "r"(a[0]), "r"(a[1]), "r"(a[2]), "r"(a[3]), "r"(b[0]), "r"(b[1]));
}
__device__ __forceinline__ void ldsm_x4(uint32_t* r, uint32_t addr) {
    asm volatile("ldmatrix.sync.aligned.m8n8.x4.shared.b16 {%0,%1,%2,%3}, [%4];"
        : "=r"(r[0]), "=r"(r[1]), "=r"(r[2]), "=r"(r[3]) : "r"(addr));
}

// ============ bf16 MMA block (3-term / 1-term), bf16 SMEM, stride K+8 ============
template <int K, int NOUT, int TM, int TERMS = 3>
__device__ __forceinline__ void mma_block(
    uint32_t sAh, uint32_t sAl, uint32_t sBh, uint32_t sBl,
    int wid, int lane, float acc[][4])
{
    constexpr int WC = (NOUT == 256) ? 8 : 4;
    constexpr int WR = 16 / WC;
    constexpr int MT = TM / (WR * 16);
    constexpr int NT = NOUT / (8 * WC);
    constexpr int NB = NT / 2;
    constexpr int LDSK = K + 8;
    const int wr = wid / WC, wc = wid % WC;
    const int mbase = wr * (MT * 16);
    const int nbase = wc * (NT * 8);
    const int lrow = lane & 15, lhalf = lane >> 4;
    const int seg = lane >> 3;
    const int brow = ((seg >> 1) << 3) + (lane & 7);
    const int bk = (seg & 1) * 8;

    #pragma unroll
    for (int i = 0; i < MT * NT; i++)
        #pragma unroll
        for (int j = 0; j < 4; j++) acc[i][j] = 0.f;

    uint32_t aoffs[MT], boffs[NB];
    #pragma unroll
    for (int mt = 0; mt < MT; mt++)
        aoffs[mt] = ((mbase + mt * 16 + lrow) * LDSK + 8 * lhalf) * 2;
    #pragma unroll
    for (int p = 0; p < NB; p++)
        boffs[p] = ((nbase + p * 16 + brow) * LDSK + bk) * 2;

    #pragma unroll
    for (int k0 = 0; k0 < K; k0 += 16) {
        const uint32_t koff = k0 * 2;
        uint32_t bh[NB][4], bl[NB][4];
        #pragma unroll
        for (int p = 0; p < NB; p++) {
            ldsm_x4(bh[p], sBh + boffs[p] + koff);
            if (TERMS == 3) ldsm_x4(bl[p], sBl + boffs[p] + koff);
        }
        #pragma unroll
        for (int mt = 0; mt < MT; mt++) {
            uint32_t ah[4], al[4];
            ldsm_x4(ah, sAh + aoffs[mt] + koff);
            if (TERMS == 3) ldsm_x4(al, sAl + aoffs[mt] + koff);
            #pragma unroll
            for (int nt = 0; nt < NT; nt++) {
                const uint32_t* bhf = &bh[nt >> 1][(nt & 1) * 2];
                float* a = acc[mt * NT + nt];
                if (TERMS == 3) {
                    const uint32_t* blf = &bl[nt >> 1][(nt & 1) * 2];
                    mma_bf16(a, al, bhf);
                    mma_bf16(a, ah, blf);
                }
                mma_bf16(a, ah, bhf);
            }
        }
    }
}

// ============ tf32 1-term MMA block, fp32 SMEM tiles, stride K+4 floats ============
template <int K, int NOUT, int TM>
__device__ __forceinline__ void mma_block_t32(
    uint32_t sA, uint32_t sB, int wid, int lane, float acc[][4])
{
    constexpr int WC = (NOUT == 256) ? 8 : 4;
    constexpr int WR = 16 / WC;
    constexpr int MT = TM / (WR * 16);
    constexpr int NT = NOUT / (8 * WC);
    constexpr int NG = NT / 2;
    constexpr int LDSK = K + 4;
    const int wr = wid / WC, wc = wid % WC;
    const int mbase = wr * (MT * 16);
    const int nbase = wc * (NT * 8);

    #pragma unroll
    for (int i = 0; i < MT * NT; i++)
        #pragma unroll
        for (int j = 0; j < 4; j++) acc[i][j] = 0.f;

    const int arow = ((lane >> 3) & 1) * 8 + (lane & 7);
    const int akof = (lane >> 4) * 4;
    const int brow = ((lane >> 4) & 1) * 8 + (lane & 7);
    const int bkof = ((lane >> 3) & 1) * 4;

    uint32_t aaddr[MT], baddr[NG];
    #pragma unroll
    for (int mt = 0; mt < MT; mt++)
        aaddr[mt] = sA + ((mbase + mt * 16 + arow) * LDSK + akof) * 4;
    #pragma unroll
    for (int gp = 0; gp < NG; gp++)
        baddr[gp] = sB + ((nbase + gp * 16 + brow) * LDSK + bkof) * 4;

    #pragma unroll
    for (int k0 = 0; k0 < K; k0 += 8) {
        const uint32_t koff = k0 * 4;
        uint32_t bf[NG][4];
        #pragma unroll
        for (int gp = 0; gp < NG; gp++)
            ldsm_x4(bf[gp], baddr[gp] + koff);
        #pragma unroll
        for (int mt = 0; mt < MT; mt++) {
            uint32_t af[4];
            ldsm_x4(af, aaddr[mt] + koff);
            #pragma unroll
            for (int nt = 0; nt < NT; nt++)
                mma_tf32(acc[mt * NT + nt], af, &bf[nt >> 1][(nt & 1) * 2]);
        }
    }
}

// ---- bf16 hi/lo epilogue into SMEM ----
template <int NOUT, int TM, bool RELU>
__device__ __forceinline__ void epi_smem(
    float acc[][4], const float* __restrict__ bias,
    __nv_bfloat16* Dh, __nv_bfloat16* Dl, int wid, int lane)
{
    constexpr int WC = (NOUT == 256) ? 8 : 4;
    constexpr int WR = 16 / WC;
    constexpr int MT = TM / (WR * 16);
    constexpr int NT = NOUT / (8 * WC);
    constexpr int LDSO = NOUT + 8;
    const int wr = wid / WC, wc = wid % WC;
    const int mbase = wr * (MT * 16);
    const int nbase = wc * (NT * 8);
    const int g = lane >> 2, t = lane & 3;
    #pragma unroll
    for (int mt = 0; mt < MT; mt++)
        #pragma unroll
        for (int half = 0; half < 2; half++) {
            int r = mbase + mt * 16 + g + half * 8;
            #pragma unroll
            for (int nt = 0; nt < NT; nt++) {
                int col = nbase + nt * 8 + 2 * t;
                float ox = acc[mt * NT + nt][half * 2 + 0] + bias[col];
                float oy = acc[mt * NT + nt][half * 2 + 1] + bias[col + 1];
                if (RELU) { ox = fmaxf(ox, 0.f); oy = fmaxf(oy, 0.f); }
                float hx = __bfloat162float(__float2bfloat16(ox));
                float hy = __bfloat162float(__float2bfloat16(oy));
                *(uint32_t*)(Dh + r * LDSO + col) = pack_bf16(ox, oy);
                *(uint32_t*)(Dl + r * LDSO + col) = pack_bf16(ox - hx, oy - hy);
            }
        }
}

// ---- tf32 epilogue into fp32 SMEM tile (stride NOUT+4), relu + tf32 round ----
template <int NOUT, int TM>
__device__ __forceinline__ void epi_smem_t32(
    float acc[][4], const float* __restrict__ bias,
    float* D, int wid, int lane)
{
    constexpr int WC = (NOUT == 256) ? 8 : 4;
    constexpr int WR = 16 / WC;
    constexpr int MT = TM / (WR * 16);
    constexpr int NT = NOUT / (8 * WC);
    constexpr int LDSO = NOUT + 4;
    const int wr = wid / WC, wc = wid % WC;
    const int mbase = wr * (MT * 16);
    const int nbase = wc * (NT * 8);
    const int g = lane >> 2, t = lane & 3;
    #pragma unroll
    for (int mt = 0; mt < MT; mt++)
        #pragma unroll
        for (int half = 0; half < 2; half++) {
            int r = mbase + mt * 16 + g + half * 8;
            #pragma unroll
            for (int nt = 0; nt < NT; nt++) {
                int col = nbase + nt * 8 + 2 * t;
                float ox = fmaxf(acc[mt * NT + nt][half * 2 + 0] + bias[col], 0.f);
                float oy = fmaxf(acc[mt * NT + nt][half * 2 + 1] + bias[col + 1], 0.f);
                float2 o; o.x = to_tf32(ox); o.y = to_tf32(oy);
                *(float2*)(D + r * LDSO + col) = o;
            }
        }
}

// ================= fused prep MLP (bf16 3-term) =================
__global__ void __launch_bounds__(512, 1)
fused_prep(const float* __restrict__ x, const float* __restrict__ W1,
           const float* __restrict__ b1,
           const __nv_bfloat16* __restrict__ B2h_g, const __nv_bfloat16* __restrict__ B2l_g,
           const __nv_bfloat16* __restrict__ B3h_g, const __nv_bfloat16* __restrict__ B3l_g,
           const float* __restrict__ b2, const float* __restrict__ b3,
           __nv_bfloat16* __restrict__ H0h, __nv_bfloat16* __restrict__ H0l,
           float* __restrict__ H0f, int N)
{
    extern __shared__ __nv_bfloat16 sm[];
    constexpr int O_B2H = 0, O_B2L = 9216;
    constexpr int O_B3H = 18432, O_B3L = 35840;
    constexpr int O_T1H = 53248, O_T1L = 57856;
    constexpr int O_T2H = 62464, O_T2L = 71168;
    constexpr int O_F32 = 79872;
    float* xs  = (float*)(sm + O_F32);
    float* w1s = xs + 64 * 6;
    float* b1s = w1s + 320;

    const int tid = threadIdx.x, wid = tid >> 5, lane = tid & 31;
    const uint32_t sb = smem_u32(sm);

    for (int s = tid; s < 128 * 8; s += 512) {
        int r = s >> 3, c = s & 7;
        ((uint4*)(sm + O_B2H + r * 72))[c] = ((const uint4*)(B2h_g + r * 64))[c];
        ((uint4*)(sm + O_B2L + r * 72))[c] = ((const uint4*)(B2l_g + r * 64))[c];
    }
    for (int s = tid; s < 128 * 16; s += 512) {
        int r = s >> 4, c = s & 15;
        ((uint4*)(sm + O_B3H + r * 136))[c] = ((const uint4*)(B3h_g + r * 128))[c];
        ((uint4*)(sm + O_B3L + r * 136))[c] = ((const uint4*)(B3l_g + r * 128))[c];
    }
    if (tid < 320) w1s[tid] = W1[tid];
    if (tid < 64)  b1s[tid] = b1[tid];

    const int ntiles = (N + 63) / 64;
    for (int tile = blockIdx.x; tile < ntiles; tile += gridDim.x) {
        const int m0 = tile * 64;
        __syncthreads();
        if (tid < 320) {
            int r = tid / 5, c = tid % 5;
            int rg = m0 + r; if (rg > N - 1) rg = N - 1;
            xs[r * 6 + c] = x[(size_t)rg * 5 + c];
        }
        __syncthreads();
        #pragma unroll
        for (int it = 0; it < 4; it++) {
            int s = tid + it * 512;
            int r = s >> 5, cp = s & 31, c = cp * 2;
            float v0 = b1s[c], v1 = b1s[c + 1];
            #pragma unroll
            for (int f = 0; f < 5; f++) {
                float xf = xs[r * 6 + f];
                v0 += xf * w1s[f * 64 + c];
                v1 += xf * w1s[f * 64 + c + 1];
            }
            v0 = fmaxf(v0, 0.f); v1 = fmaxf(v1, 0.f);
            float h0v = __bfloat162float(__float2bfloat16(v0));
            float h1v = __bfloat162float(__float2bfloat16(v1));
            *(uint32_t*)(sm + O_T1H + r * 72 + c) = pack_bf16(v0, v1);
            *(uint32_t*)(sm + O_T1L + r * 72 + c) = pack_bf16(v0 - h0v, v1 - h1v);
        }
        __syncthreads();
        {
            float acc[4][4];
            mma_block<64, 128, 64>(sb + O_T1H * 2, sb + O_T1L * 2,
                                   sb + O_B2H * 2, sb + O_B2L * 2, wid, lane, acc);
            epi_smem<128, 64, true>(acc, b2, sm + O_T2H, sm + O_T2L, wid, lane);
        }
        __syncthreads();
        {
            float acc[4][4];
            mma_block<128, 128, 64>(sb + O_T2H * 2, sb + O_T2L * 2,
                                    sb + O_B3H * 2, sb + O_B3L * 2, wid, lane, acc);
            const int wr = wid / 4, wc = wid % 4;
            const int mbase = wr * 16, nbase = wc * 32;
            const int g = lane >> 2, t = lane & 3;
            #pragma unroll
            for (int half = 0; half < 2; half++) {
                int r = mbase + g + half * 8;
                int rg = m0 + r;
                if (rg >= N) continue;
                #pragma unroll
                for (int nt = 0; nt < 4; nt++) {
                    int col = nbase + nt * 8 + 2 * t;
                    float ox = acc[nt][half * 2 + 0] + b3[col];
                    float oy = acc[nt][half * 2 + 1] + b3[col + 1];
                    float hx = __bfloat162float(__float2bfloat16(ox));
                    float hy = __bfloat162float(__float2bfloat16(oy));
                    size_t idx = ((size_t)rg * 128 + col) >> 1;
                    ((uint32_t*)H0h)[idx] = pack_bf16(ox, oy);
                    ((uint32_t*)H0l)[idx] = pack_bf16(ox - hx, oy - hy);
                    // tf32(hi+lo) for the sv kernel
                    float rx = hx + __bfloat162float(__float2bfloat16(ox - hx));
                    float ry = hy + __bfloat162float(__float2bfloat16(oy - hy));
                    float2 f; f.x = to_tf32(rx); f.y = to_tf32(ry);
                    *(float2*)(H0f + (size_t)rg * 128 + col) = f;
                }
            }
        }
    }
}

// ================= single projection: h0(128) -> 128, bf16 1-term =================
// OMODE 0: fp32 -> Q (row stride 256). OMODE 1: bf16 -> Kb (row stride 128).
template <int OMODE>
__global__ void __launch_bounds__(512, 1)
gemm_p128(const __nv_bfloat16* __restrict__ Ahg,
          const __nv_bfloat16* __restrict__ Bth,
          const float* __restrict__ bias,
          float* __restrict__ Q, __nv_bfloat16* __restrict__ Kb, int M)
{
    extern __shared__ __nv_bfloat16 sm[];
    constexpr int O_BH = 0;                       // [128][136]
    constexpr int O_AH = 17408;                   // [64][136]
    const int tid = threadIdx.x, wid = tid >> 5, lane = tid & 31;
    const uint32_t sb = smem_u32(sm);

    for (int s = tid; s < 128 * 16; s += 512) {
        int r = s >> 4, c = s & 15;
        ((uint4*)(sm + O_BH + r * 136))[c] = ((const uint4*)(Bth + r * 128))[c];
    }

    const int ntiles = (M + 63) / 64;
    for (int tile = blockIdx.x; tile < ntiles; tile += gridDim.x) {
        const int m0 = tile * 64;
        __syncthreads();
        #pragma unroll
        for (int it = 0; it < 2; it++) {
            int s = tid + it * 512;
            int r = s >> 4, c = s & 15;
            int rg = m0 + r; if (rg > M - 1) rg = M - 1;
            ((uint4*)(sm + O_AH + r * 136))[c] = ((const uint4*)(Ahg + (size_t)rg * 128))[c];
        }
        __syncthreads();
        float acc[4][4];
        mma_block<128, 128, 64, 1>(sb + O_AH * 2, 0, sb + O_BH * 2, 0, wid, lane, acc);
        const int wr = wid / 4, wc = wid % 4;
        const int mbase = wr * 16, nbase = wc * 32;
        const int g = lane >> 2, t = lane & 3;
        #pragma unroll
        for (int half = 0; half < 2; half++) {
            int r = mbase + g + half * 8;
            int rg = m0 + r;
            if (rg >= M) continue;
            #pragma unroll
            for (int nt = 0; nt < 4; nt++) {
                int col = nbase + nt * 8 + 2 * t;
                float ox = acc[nt][half * 2 + 0] + bias[col];
                float oy = acc[nt][half * 2 + 1] + bias[col + 1];
                if (OMODE == 0) {
                    float2 o; o.x = ox; o.y = oy;
                    *(float2*)(Q + (size_t)rg * 256 + col) = o;
                } else {
                    *(uint32_t*)(Kb + (size_t)rg * 128 + col) = pack_bf16(ox, oy);
                }
            }
        }
    }
}

// ================= sv projection: tf32 1-term (A from h0f) =================
__global__ void __launch_bounds__(512, 1)
gemm_sv_t32(const float* __restrict__ Af,          // [M][128] tf32-rounded
            const float* __restrict__ Btf,          // [256][128] tf32-rounded
            const float* __restrict__ bias,
            float* __restrict__ S, float* __restrict__ V, int M)
{
    extern __shared__ float smf[];
    constexpr int O_B = 0;                    // [256][132]
    constexpr int O_A = 256 * 132;            // [64][132]
    const int tid = threadIdx.x, wid = tid >> 5, lane = tid & 31;
    const uint32_t sb = smem_u32(smf);

    for (int s = tid; s < 256 * 32; s += 512) {
        int r = s >> 5, c = s & 31;
        ((float4*)(smf + O_B + r * 132))[c] = ((const float4*)(Btf + r * 128))[c];
    }

    const int ntiles = (M + 63) / 64;
    for (int tile = blockIdx.x; tile < ntiles; tile += gridDim.x) {
        const int m0 = tile * 64;
        __syncthreads();
        #pragma unroll
        for (int it = 0; it < 4; it++) {
            int s = tid + it * 512;                    // 64 rows x 32 float4 chunks
            int r = s >> 5, c = s & 31;
            int rg = m0 + r; if (rg > M - 1) rg = M - 1;
            ((float4*)(smf + O_A + r * 132))[c] = ((const float4*)(Af + (size_t)rg * 128))[c];
        }
        __syncthreads();
        float acc[8][4];
        mma_block_t32<128, 256, 64>(sb + O_A * 4, sb + O_B * 4, wid, lane, acc);
        const int wr = wid / 8, wc = wid % 8;
        const int mbase = wr * 32, nbase = wc * 32;
        const int g = lane >> 2, t = lane & 3;
        #pragma unroll
        for (int mt = 0; mt < 2; mt++)
            #pragma unroll
            for (int half = 0; half < 2; half++) {
                int r = mbase + mt * 16 + g + half * 8;
                int rg = m0 + r;
                if (rg >= M) continue;
                #pragma unroll
                for (int nt = 0; nt < 4; nt++) {
                    int col = nbase + nt * 8 + 2 * t;
                    float2 o;
                    o.x = acc[mt * 4 + nt][half * 2 + 0] + bias[col];
                    o.y = acc[mt * 4 + nt][half * 2 + 1] + bias[col + 1];
                    if (col < 128)
                        *(float2*)(S + (size_t)rg * 256 + 128 + col) = o;
                    else
                        *(float2*)(V + (size_t)rg * 128 + (col - 128)) = o;
                }
            }
    }
}

// ================= fused update MLP: tf32 1-term (+resid) =================
__global__ void __launch_bounds__(512, 1)
fused_update_t32(const float* __restrict__ H1,
                 const float* __restrict__ W1f, const float* __restrict__ W2f,
                 const float* __restrict__ W3f,
                 const float* __restrict__ ub1, const float* __restrict__ ub2,
                 const float* __restrict__ ub3, float* __restrict__ out, int N)
{
    extern __shared__ float smf[];
    constexpr int O_W1 = 0;
    constexpr int O_W2 = 8448;
    constexpr int O_W3 = 17152;
    constexpr int O_H1 = 34048;
    constexpr int O_T1 = 42496;
    constexpr int O_T2 = 46848;
    const int tid = threadIdx.x, wid = tid >> 5, lane = tid & 31;
    const uint32_t sb = smem_u32(smf);

    for (int s = tid; s < 64 * 32; s += 512) {
        int r = s >> 5, c = s & 31;
        ((float4*)(smf + O_W1 + r * 132))[c] = ((const float4*)(W1f + r * 128))[c];
    }
    for (int s = tid; s < 128 * 16; s += 512) {
        int r = s >> 4, c = s & 15;
        ((float4*)(smf + O_W2 + r * 68))[c] = ((const float4*)(W2f + r * 64))[c];
    }
    for (int s = tid; s < 128 * 32; s += 512) {
        int r = s >> 5, c = s & 31;
        ((float4*)(smf + O_W3 + r * 132))[c] = ((const float4*)(W3f + r * 128))[c];
    }

    const int ntiles = (N + 63) / 64;
    for (int tile = blockIdx.x; tile < ntiles; tile += gridDim.x) {
        const int m0 = tile * 64;
        __syncthreads();
        #pragma unroll
        for (int it = 0; it < 4; it++) {
            int s = tid + it * 512;
            int r = s >> 5, c = s & 31;
            int rg = m0 + r; if (rg > N - 1) rg = N - 1;
            float4 v = ((const float4*)(H1 + (size_t)rg * 128))[c];
            v.x = to_tf32(v.x); v.y = to_tf32(v.y);
            v.z = to_tf32(v.z); v.w = to_tf32(v.w);
            ((float4*)(smf + O_H1 + r * 132))[c] = v;
        }
        __syncthreads();
        {
            float acc[2][4];
            mma_block_t32<128, 64, 64>(sb + O_H1 * 4, sb + O_W1 * 4, wid, lane, acc);
            epi_smem_t32<64, 64>(acc, ub1, smf + O_T1, wid, lane);
        }
        __syncthreads();
        {
            float acc[4][4];
            mma_block_t32<64, 128, 64>(sb + O_T1 * 4, sb + O_W2 * 4, wid, lane, acc);
            epi_smem_t32<128, 64>(acc, ub2, smf + O_T2, wid, lane);
        }
        __syncthreads();
        {
            float acc[4][4];
            mma_block_t32<128, 128, 64>(sb + O_T2 * 4, sb + O_W3 * 4, wid, lane, acc);
            const int wr = wid / 4, wc = wid % 4;
            const int mbase = wr * 16, nbase = wc * 32;
            const int g = lane >> 2, t = lane & 3;
            #pragma unroll
            for (int half = 0; half < 2; half++) {
                int r = mbase + g + half * 8;
                int rg = m0 + r;
                if (rg >= N) continue;
                #pragma unroll
                for (int nt = 0; nt < 4; nt++) {
                    int col = nbase + nt * 8 + 2 * t;
                    float2 rv = *(const float2*)(H1 + (size_t)rg * 128 + col);
                    float2 o;
                    o.x = acc[nt][half * 2 + 0] + ub3[col] + rv.x;
                    o.y = acc[nt][half * 2 + 1] + ub3[col + 1] + rv.y;
                    *(float2*)(out + (size_t)rg * 128 + col) = o;
                }
            }
        }
    }
}

// ---------------- transpose weights ----------------
// slots: 0=pW2 1=pW3 2=qW 3=kW 4=sW 5=vW 6=uW1 7=uW2 8=uW3
__global__ void transpose_all(const float* s0, const float* s1, const float* s2,
                              const float* s3, const float* s4, const float* s5,
                              const float* s6, const float* s7, const float* s8)
{
    const int Ks[9] = {64, 128, 128, 128, 128, 128, 128, 64, 128};
    const int Ns[9] = {128, 128, 128, 128, 128, 128, 64, 128, 128};
    const float* srcs[9] = {s0, s1, s2, s3, s4, s5, s6, s7, s8};
    int z = blockIdx.z;
    const float* src = srcs[z];
    __nv_bfloat16* dh = g_wth + z * 16384;
    __nv_bfloat16* dl = g_wtl + z * 16384;
    float* df = (z >= 4) ? (g_wtf + (z - 4) * 16384) : nullptr;
    int K = Ks[z], Nc = Ns[z];
    __shared__ float tile[32][33];
    int bx = blockIdx.x * 32, by = blockIdx.y * 32;
    int tx = threadIdx.x, ty = threadIdx.y;
    #pragma unroll
    for (int i = 0; i < 32; i += 8) {
        int k = by + ty + i, n = bx + tx;
        if (k < K && n < Nc) tile[ty + i][tx] = src[(long)k * Nc + n];
    }
    __syncthreads();
    #pragma unroll
    for (int i = 0; i < 32; i += 8) {
        int n = bx + ty + i, k = by + tx;
        if (n < Nc && k < K) {
            float v = tile[tx][ty + i];
            __nv_bfloat16 h = __float2bfloat16(v);
            dh[(long)n * K + k] = h;
            dl[(long)n * K + k] = __float2bfloat16(v - __bfloat162float(h));
            if (df) df[(long)n * K + k] = to_tf32(v);
        }
    }
}

__global__ void concat_bias(const float* qb, const float* kb,
                            const float* sb, const float* vb)
{
    int i = threadIdx.x;
    float v = (i < 128) ? qb[i] : (i < 256) ? kb[i - 128]
            : (i < 384) ? sb[i - 256] : vb[i - 384];
    g_bcat[i] = v;
}

// ---------------- CSR build ----------------
__global__ void zero_cnt_kernel(int N)
{
    int i = blockIdx.x * blockDim.x + threadIdx.x;
    if (i < N) g_cnt[i] = 0;
}
__global__ void hist_kernel(const int* __restrict__ dst, int E)
{
    int e = blockIdx.x * blockDim.x + threadIdx.x;
    if (e < E) g_pos[e] = atomicAdd(&g_cnt[dst[e]], 1);
}
__global__ void scan1_kernel(int N)
{
    __shared__ int sh[1024];
    int i = blockIdx.x * 1024 + threadIdx.x;
    int v = (i < N) ? g_cnt[i] : 0;
    sh[threadIdx.x] = v;
    __syncthreads();
    for (int d = 1; d < 1024; d <<= 1) {
        int tmp = (threadIdx.x >= d) ? sh[threadIdx.x - d] : 0;
        __syncthreads();
        sh[threadIdx.x] += tmp;
        __syncthreads();
    }
    if (i < N) g_off[i] = sh[threadIdx.x] - v;
    if (threadIdx.x == 1023) g_bsum[blockIdx.x] = sh[1023];
}
__global__ void scan2_kernel(int nb)
{
    if (blockIdx.x == 0 && threadIdx.x == 0) {
        int run = 0;
        for (int i = 0; i < nb; i++) { int v = g_bsum[i]; g_bsum[i] = run; run += v; }
    }
}
__global__ void scan3_kernel(int N, int E)
{
    int i = blockIdx.x * blockDim.x + threadIdx.x;
    if (i < N) g_off[i] += g_bsum[i >> 10];
    if (i == 0) g_off[N] = E;
}
__global__ void scatter_kernel(const int* __restrict__ src, const int* __restrict__ dst, int E)
{
    int e = blockIdx.x * blockDim.x + threadIdx.x;
    if (e < E) g_esrc[g_off[dst[e]] + g_pos[e]] = src[e];
}

// ---------------- attention: one warp per destination node ----------------
__global__ void attn_kernel(int N)
{
    int gtid = blockIdx.x * blockDim.x + threadIdx.x;
    int n    = gtid >> 5;
    int lane = threadIdx.x & 31;
    if (n >= N) return;

    const float4* qs4 = reinterpret_cast<const float4*>(g_qs);
    const uint2*  kb2 = reinterpret_cast<const uint2*>(g_kb);
    const float4* v4  = reinterpret_cast<const float4*>(g_v);

    float4 ql = qs4[(long)n * 64 + lane];
    int e0 = g_off[n], e1 = g_off[n + 1];

    const float scale = 0.17677669529663687f;
    float s0 = 0.f, s1 = 0.f;
    float4 a0 = make_float4(0.f, 0.f, 0.f, 0.f);
    float4 a1 = make_float4(0.f, 0.f, 0.f, 0.f);

    int e = e0;
    for (; e + 2 <= e1; e += 2) {
        int src0 = __ldg(&g_esrc[e]);
        int src1 = __ldg(&g_esrc[e + 1]);
        uint2 kw0 = kb2[(long)src0 * 32 + lane];
        uint2 kw1 = kb2[(long)src1 * 32 + lane];
        float4 v0 = v4[(long)src0 * 32 + lane];
        float4 v1 = v4[(long)src1 * 32 + lane];
        float2 k0a = __bfloat1622float2(*reinterpret_cast<__nv_bfloat162*>(&kw0.x));
        float2 k0b = __bfloat1622float2(*reinterpret_cast<__nv_bfloat162*>(&kw0.y));
        float2 k1a = __bfloat1622float2(*reinterpret_cast<__nv_bfloat162*>(&kw1.x));
        float2 k1b = __bfloat1622float2(*reinterpret_cast<__nv_bfloat162*>(&kw1.y));
        float p0 = ql.x * k0a.x + ql.y * k0a.y + ql.z * k0b.x + ql.w * k0b.y;
        float p1 = ql.x * k1a.x + ql.y * k1a.y + ql.z * k1b.x + ql.w * k1b.y;
        p0 += __shfl_xor_sync(0xffffffffu, p0, 1);
        p1 += __shfl_xor_sync(0xffffffffu, p1, 1);
        p0 += __shfl_xor_sync(0xffffffffu, p0, 2);
        p1 += __shfl_xor_sync(0xffffffffu, p1, 2);
        p0 += __shfl_xor_sync(0xffffffffu, p0, 4);
        p1 += __shfl_xor_sync(0xffffffffu, p1, 4);
        float w0 = __expf(p0 * scale);
        float w1 = __expf(p1 * scale);
        s0 += w0; s1 += w1;
        a0.x += w0 * v0.x; a0.y += w0 * v0.y; a0.z += w0 * v0.z; a0.w += w0 * v0.w;
        a1.x += w1 * v1.x; a1.y += w1 * v1.y; a1.z += w1 * v1.z; a1.w += w1 * v1.w;
    }
    if (e < e1) {
        int src0 = __ldg(&g_esrc[e]);
        uint2 kw0 = kb2[(long)src0 * 32 + lane];
        float4 v0 = v4[(long)src0 * 32 + lane];
        float2 k0a = __bfloat1622float2(*reinterpret_cast<__nv_bfloat162*>(&kw0.x));
        float2 k0b = __bfloat1622float2(*reinterpret_cast<__nv_bfloat162*>(&kw0.y));
        float p0 = ql.x * k0a.x + ql.y * k0a.y + ql.z * k0b.x + ql.w * k0b.y;
        p0 += __shfl_xor_sync(0xffffffffu, p0, 1);
        p0 += __shfl_xor_sync(0xffffffffu, p0, 2);
        p0 += __shfl_xor_sync(0xffffffffu, p0, 4);
        float w0 = __expf(p0 * scale);
        s0 += w0;
        a0.x += w0 * v0.x; a0.y += w0 * v0.y; a0.z += w0 * v0.z; a0.w += w0 * v0.w;
    }
    float s = s0 + s1;
    float inv = (s > 0.f) ? (1.f / s) : 0.f;
    float4 sk = qs4[(long)n * 64 + 32 + lane];
    float4 o;
    o.x = (a0.x + a1.x) * inv + sk.x;
    o.y = (a0.y + a1.y) * inv + sk.y;
    o.z = (a0.z + a1.z) * inv + sk.z;
    o.w = (a0.w + a1.w) * inv + sk.w;
    ((float4*)g_h1f)[(long)n * 32 + lane] = o;
}

// ---------------- host ----------------
extern "C" void kernel_launch(void* const* d_in, const int* in_sizes, int n_in,
                              void* d_out, int out_size)
{
    const float* x    = (const float*)d_in[0];
    const int*   ei   = (const int*)  d_in[1];
    const float* pW1  = (const float*)d_in[2];
    const float* pb1  = (const float*)d_in[3];
    const float* pW2  = (const float*)d_in[4];
    const float* pb2  = (const float*)d_in[5];
    const float* pW3  = (const float*)d_in[6];
    const float* pb3  = (const float*)d_in[7];
    const float* uW1  = (const float*)d_in[8];
    const float* ub1  = (const float*)d_in[9];
    const float* uW2  = (const float*)d_in[10];
    const float* ub2  = (const float*)d_in[11];
    const float* uW3  = (const float*)d_in[12];
    const float* ub3  = (const float*)d_in[13];
    const float* qW   = (const float*)d_in[14];
    const float* qb   = (const float*)d_in[15];
    const float* kW   = (const float*)d_in[16];
    const float* kb   = (const float*)d_in[17];
    const float* vW   = (const float*)d_in[18];
    const float* vb   = (const float*)d_in[19];
    const float* sW   = (const float*)d_in[20];
    const float* sb   = (const float*)d_in[21];
    float* out = (float*)d_out;

    const int F = 5;
    const int N = in_sizes[0] / F;
    const int E = in_sizes[1] / 2;
    const int* src = ei;
    const int* dst = ei + E;

    __nv_bfloat16 *h0h, *h0l, *wh, *wl, *kbuf;
    float *qs, *vbuf, *bc, *h0f, *h1f, *wf;
    cudaGetSymbolAddress((void**)&h0h,  g_h0h);
    cudaGetSymbolAddress((void**)&h0l,  g_h0l);
    cudaGetSymbolAddress((void**)&h0f,  g_h0f);
    cudaGetSymbolAddress((void**)&h1f,  g_h1f);
    cudaGetSymbolAddress((void**)&qs,   g_qs);
    cudaGetSymbolAddress((void**)&kbuf, g_kb);
    cudaGetSymbolAddress((void**)&vbuf, g_v);
    cudaGetSymbolAddress((void**)&bc,   g_bcat);
    cudaGetSymbolAddress((void**)&wh,   g_wth);
    cudaGetSymbolAddress((void**)&wl,   g_wtl);
    cudaGetSymbolAddress((void**)&wf,   g_wtf);

    // ---- fork CSR build onto side stream ----
    cudaEventRecord(g_ev_fork, 0);
    cudaStreamWaitEvent(g_s2, g_ev_fork, 0);
    {
        int nb1024 = (N + 1023) / 1024;
        zero_cnt_kernel<<<(N + 255) / 256, 256, 0, g_s2>>>(N);
        hist_kernel<<<(E + 255) / 256, 256, 0, g_s2>>>(dst, E);
        scan1_kernel<<<nb1024, 1024, 0, g_s2>>>(N);
        scan2_kernel<<<1, 32, 0, g_s2>>>(nb1024);
        scan3_kernel<<<(N + 255) / 256, 256, 0, g_s2>>>(N, E);
        scatter_kernel<<<(E + 255) / 256, 256, 0, g_s2>>>(src, dst, E);
    }

    // ---- main chain ----
    {
        dim3 tgrid(4, 4, 9), tblk(32, 8);
        transpose_all<<<tgrid, tblk>>>(pW2, pW3, qW, kW, sW, vW, uW1, uW2, uW3);
        concat_bias<<<1, 512>>>(qb, kb, sb, vb);
    }
    {
        int smem = 162816;
        cudaFuncSetAttribute(fused_prep, cudaFuncAttributeMaxDynamicSharedMemorySize, smem);
        fused_prep<<<148, 512, smem>>>(x, pW1, pb1,
            wh + 0 * 16384, wl + 0 * 16384, wh + 1 * 16384, wl + 1 * 16384,
            pb2, pb3, h0h, h0l, h0f, N);
    }
    cudaEventRecord(g_ev_prep, 0);

    // q and k (52 KB SMEM each) on side stream — co-resident with sv (169 KB) on main
    cudaStreamWaitEvent(g_s2, g_ev_prep, 0);
    {
        int smemA = 17408 * 2 + 34816;   // 69,632 B... (B 34,816 + A 17,408) * 2B elems
        smemA = (17408 + 34816);          // bf16 elements count
        smemA = (128 * 136 + 64 * 136) * 2;  // = 52,224 bytes
        cudaFuncSetAttribute(gemm_p128<0>, cudaFuncAttributeMaxDynamicSharedMemorySize, smemA);
        cudaFuncSetAttribute(gemm_p128<1>, cudaFuncAttributeMaxDynamicSharedMemorySize, smemA);
        gemm_p128<0><<<148, 512, smemA, g_s2>>>(h0h, wh + 2 * 16384, bc,       qs, nullptr, N);
        gemm_p128<1><<<148, 512, smemA, g_s2>>>(h0h, wh + 3 * 16384, bc + 128, nullptr, kbuf, N);
        cudaEventRecord(g_ev_join, g_s2);
    }
    {
        int smemB = (256 * 132 + 64 * 132) * 4;  // 168,960 B
        cudaFuncSetAttribute(gemm_sv_t32, cudaFuncAttributeMaxDynamicSharedMemorySize, smemB);
        gemm_sv_t32<<<148, 512, smemB>>>(h0f, wf + 0 * 16384, bc + 256, qs, vbuf, N);
    }

    cudaStreamWaitEvent(0, g_ev_join, 0);

    long tt = (long)N * 32;
    attn_kernel<<<(int)((tt + 255) / 256), 256>>>(N);

    {
        int smem = 55296 * 4;
        cudaFuncSetAttribute(fused_update_t32, cudaFuncAttributeMaxDynamicSharedMemorySize, smem);
        fused_update_t32<<<148, 512, smem>>>(h1f,
            wf + 2 * 16384, wf + 3 * 16384, wf + 4 * 16384,
            ub1, ub2, ub3, out, N);
    }
}

// round 14
// speedup vs baseline: 1.0666x; 1.0666x over previous
#include <cuda_runtime.h>
#include <cuda_bf16.h>
#include <cstdint>
#include <math.h>

#define MAXN 100000
#define MAXE 800000

// ---------------- device scratch ----------------
__device__ __nv_bfloat16 g_h0h[MAXN * 128];  // h0 bf16 (for qk)
__device__ float g_h0f[MAXN * 128];          // h0 tf32-rounded fp32 (for sv)
__device__ float g_h1f[MAXN * 128];          // h1 fp32 (attention out)
__device__ float g_qs[MAXN * 256];           // cols 0-127: q, 128-255: skip (fp32)
__device__ __nv_bfloat16 g_kb[MAXN * 128];   // k (bf16)
__device__ float g_v [MAXN * 128];           // v (fp32)
__device__ __nv_bfloat16 g_wth[9 * 128 * 128];
__device__ float g_wtf[7 * 128 * 128];       // tf32 fp32: 0=pW2 1=pW3 2,3=sW|vW 4=uW1 5=uW2 6=uW3
__device__ float g_bcat[512];                // [qb|kb|sb|vb]
__device__ int   g_cnt[MAXN];
__device__ int   g_off[MAXN + 1];
__device__ int   g_bsum[256];
__device__ int   g_pos[MAXE];
__device__ int   g_esrc[MAXE];

// ---------------- side stream ----------------
static cudaStream_t g_s2;
static cudaEvent_t  g_ev_fork, g_ev_prep, g_ev_join;
namespace {
struct StreamInit {
    StreamInit() {
        cudaStreamCreateWithFlags(&g_s2, cudaStreamNonBlocking);
        cudaEventCreateWithFlags(&g_ev_fork, cudaEventDisableTiming);
        cudaEventCreateWithFlags(&g_ev_prep, cudaEventDisableTiming);
        cudaEventCreateWithFlags(&g_ev_join, cudaEventDisableTiming);
    }
};
StreamInit g_stream_init;
}

__device__ __forceinline__ uint32_t smem_u32(const void* p) {
    uint32_t a;
    asm("{ .reg .u64 t; cvta.to.shared.u64 t, %1; cvt.u32.u64 %0, t; }" : "=r"(a) : "l"(p));
    return a;
}
__device__ __forceinline__ uint32_t pack_bf16(float a, float b) {
    __nv_bfloat16 ha = __float2bfloat16(a);
    __nv_bfloat16 hb = __float2bfloat16(b);
    uint16_t ua = *(uint16_t*)&ha, ub = *(uint16_t*)&hb;
    return (uint32_t)ua | ((uint32_t)ub << 16);
}
__device__ __forceinline__ float to_tf32(float x) {
    float y; asm("cvt.rna.tf32.f32 %0, %1;" : "=f"(y) : "f"(x)); return y;
}
__device__ __forceinline__ void mma_bf16(float c[4], const uint32_t a[4], const uint32_t b[2]) {
    asm volatile(
        "mma.sync.aligned.m16n8k16.row.col.f32.bf16.bf16.f32 "
        "{%0,%1,%2,%3}, {%4,%5,%6,%7}, {%8,%9}, {%0,%1,%2,%3};"
        : "+f"(c[0]), "+f"(c[1]), "+f"(c[2]), "+f"(c[3])
        : "r"(a[0]), "r"(a[1]), "r"(a[2]), "r"(a[3]), "r"(b[0]), "r"(b[1]));
}
__device__ __forceinline__ void mma_tf32(float c[4], const uint32_t a[4], const uint32_t b[2]) {
    asm volatile(
        "mma.sync.aligned.m16n8k8.row.col.f32.tf32.tf32.f32 "
        "{%0,%1,%2,%3}, {%4,%5,%6,%7}, {%8,%9}, {%0,%1,%2,%3};"
        : "+f"(c[0]), "+f"(c[1]), "+f"(c[2]), "+f"(c[3])
        : "r"(a[0]), "r"(a[1]), "r"(a[2]), "r"(a[3]), "r"(b[0]), "r"(b[1]));
}
__device__ __forceinline__ void ldsm_x4(uint32_t* r, uint32_t addr) {
    asm volatile("ldmatrix.sync.aligned.m8n8.x4.shared.b16 {%0,%1,%2,%3}, [%4];"
        : "=r"(r[0]), "=r"(r[1]), "=r"(r[2]), "=r"(r[3]) : "r"(addr));
}

// ============ bf16 1-term MMA block, bf16 SMEM, stride K+8 ============
template <int K, int NOUT, int TM>
__device__ __forceinline__ void mma_block_b16(
    uint32_t sAh, uint32_t sBh, int wid, int lane, float acc[][4])
{
    constexpr int WC = (NOUT == 256) ? 8 : 4;
    constexpr int WR = 16 / WC;
    constexpr int MT = TM / (WR * 16);
    constexpr int NT = NOUT / (8 * WC);
    constexpr int NB = NT / 2;
    constexpr int LDSK = K + 8;
    const int wr = wid / WC, wc = wid % WC;
    const int mbase = wr * (MT * 16);
    const int nbase = wc * (NT * 8);
    const int lrow = lane & 15, lhalf = lane >> 4;
    const int seg = lane >> 3;
    const int brow = ((seg >> 1) << 3) + (lane & 7);
    const int bk = (seg & 1) * 8;

    #pragma unroll
    for (int i = 0; i < MT * NT; i++)
        #pragma unroll
        for (int j = 0; j < 4; j++) acc[i][j] = 0.f;

    uint32_t aoffs[MT], boffs[NB];
    #pragma unroll
    for (int mt = 0; mt < MT; mt++)
        aoffs[mt] = ((mbase + mt * 16 + lrow) * LDSK + 8 * lhalf) * 2;
    #pragma unroll
    for (int p = 0; p < NB; p++)
        boffs[p] = ((nbase + p * 16 + brow) * LDSK + bk) * 2;

    #pragma unroll
    for (int k0 = 0; k0 < K; k0 += 16) {
        const uint32_t koff = k0 * 2;
        uint32_t bh[NB][4];
        #pragma unroll
        for (int p = 0; p < NB; p++)
            ldsm_x4(bh[p], sBh + boffs[p] + koff);
        #pragma unroll
        for (int mt = 0; mt < MT; mt++) {
            uint32_t ah[4];
            ldsm_x4(ah, sAh + aoffs[mt] + koff);
            #pragma unroll
            for (int nt = 0; nt < NT; nt++)
                mma_bf16(acc[mt * NT + nt], ah, &bh[nt >> 1][(nt & 1) * 2]);
        }
    }
}

// ============ tf32 1-term MMA block, fp32 SMEM tiles, stride K+4 floats ============
template <int K, int NOUT, int TM>
__device__ __forceinline__ void mma_block_t32(
    uint32_t sA, uint32_t sB, int wid, int lane, float acc[][4])
{
    constexpr int WC = (NOUT == 256) ? 8 : 4;
    constexpr int WR = 16 / WC;
    constexpr int MT = TM / (WR * 16);
    constexpr int NT = NOUT / (8 * WC);
    constexpr int NG = NT / 2;
    constexpr int LDSK = K + 4;
    const int wr = wid / WC, wc = wid % WC;
    const int mbase = wr * (MT * 16);
    const int nbase = wc * (NT * 8);

    #pragma unroll
    for (int i = 0; i < MT * NT; i++)
        #pragma unroll
        for (int j = 0; j < 4; j++) acc[i][j] = 0.f;

    const int arow = ((lane >> 3) & 1) * 8 + (lane & 7);
    const int akof = (lane >> 4) * 4;
    const int brow = ((lane >> 4) & 1) * 8 + (lane & 7);
    const int bkof = ((lane >> 3) & 1) * 4;

    uint32_t aaddr[MT], baddr[NG];
    #pragma unroll
    for (int mt = 0; mt < MT; mt++)
        aaddr[mt] = sA + ((mbase + mt * 16 + arow) * LDSK + akof) * 4;
    #pragma unroll
    for (int gp = 0; gp < NG; gp++)
        baddr[gp] = sB + ((nbase + gp * 16 + brow) * LDSK + bkof) * 4;

    #pragma unroll
    for (int k0 = 0; k0 < K; k0 += 8) {
        const uint32_t koff = k0 * 4;
        uint32_t bf[NG][4];
        #pragma unroll
        for (int gp = 0; gp < NG; gp++)
            ldsm_x4(bf[gp], baddr[gp] + koff);
        #pragma unroll
        for (int mt = 0; mt < MT; mt++) {
            uint32_t af[4];
            ldsm_x4(af, aaddr[mt] + koff);
            #pragma unroll
            for (int nt = 0; nt < NT; nt++)
                mma_tf32(acc[mt * NT + nt], af, &bf[nt >> 1][(nt & 1) * 2]);
        }
    }
}

// ---- tf32 epilogue into fp32 SMEM tile (stride NOUT+4), relu + tf32 round ----
template <int NOUT, int TM>
__device__ __forceinline__ void epi_smem_t32(
    float acc[][4], const float* __restrict__ bias,
    float* D, int wid, int lane)
{
    constexpr int WC = (NOUT == 256) ? 8 : 4;
    constexpr int WR = 16 / WC;
    constexpr int MT = TM / (WR * 16);
    constexpr int NT = NOUT / (8 * WC);
    constexpr int LDSO = NOUT + 4;
    const int wr = wid / WC, wc = wid % WC;
    const int mbase = wr * (MT * 16);
    const int nbase = wc * (NT * 8);
    const int g = lane >> 2, t = lane & 3;
    #pragma unroll
    for (int mt = 0; mt < MT; mt++)
        #pragma unroll
        for (int half = 0; half < 2; half++) {
            int r = mbase + mt * 16 + g + half * 8;
            #pragma unroll
            for (int nt = 0; nt < NT; nt++) {
                int col = nbase + nt * 8 + 2 * t;
                float ox = fmaxf(acc[mt * NT + nt][half * 2 + 0] + bias[col], 0.f);
                float oy = fmaxf(acc[mt * NT + nt][half * 2 + 1] + bias[col + 1], 0.f);
                float2 o; o.x = to_tf32(ox); o.y = to_tf32(oy);
                *(float2*)(D + r * LDSO + col) = o;
            }
        }
}

// ================= fused prep MLP: x(5) ->FFMA 64 ->tf32 128 ->tf32 128 =================
// outputs: H0h bf16 (for qk), H0f tf32-fp32 (for sv)
__global__ void __launch_bounds__(512, 1)
fused_prep(const float* __restrict__ x, const float* __restrict__ W1,
           const float* __restrict__ b1,
           const float* __restrict__ B2f,   // [128][64] tf32
           const float* __restrict__ B3f,   // [128][128] tf32
           const float* __restrict__ b2, const float* __restrict__ b3,
           __nv_bfloat16* __restrict__ H0h, float* __restrict__ H0f, int N)
{
    extern __shared__ float smf[];
    constexpr int O_B2 = 0;                  // [128][68]  -> 8704
    constexpr int O_B3 = 8704;               // [128][132] -> 16896 (end 25600)
    constexpr int O_T1 = 25600;              // [64][68]   -> 4352  (end 29952)
    constexpr int O_T2 = 29952;              // [64][132]  -> 8448  (end 38400)
    constexpr int O_XW = 38400;              // xs 384 + w1 320 + b1 64
    float* xs  = smf + O_XW;                 // [64][6]
    float* w1s = xs + 384;
    float* b1s = w1s + 320;

    const int tid = threadIdx.x, wid = tid >> 5, lane = tid & 31;
    const uint32_t sb = smem_u32(smf);

    for (int s = tid; s < 128 * 16; s += 512) {
        int r = s >> 4, c = s & 15;
        ((float4*)(smf + O_B2 + r * 68))[c] = ((const float4*)(B2f + r * 64))[c];
    }
    for (int s = tid; s < 128 * 32; s += 512) {
        int r = s >> 5, c = s & 31;
        ((float4*)(smf + O_B3 + r * 132))[c] = ((const float4*)(B3f + r * 128))[c];
    }
    if (tid < 320) w1s[tid] = W1[tid];
    if (tid < 64)  b1s[tid] = b1[tid];

    const int ntiles = (N + 63) / 64;
    for (int tile = blockIdx.x; tile < ntiles; tile += gridDim.x) {
        const int m0 = tile * 64;
        __syncthreads();
        if (tid < 320) {
            int r = tid / 5, c = tid % 5;
            int rg = m0 + r; if (rg > N - 1) rg = N - 1;
            xs[r * 6 + c] = x[(size_t)rg * 5 + c];
        }
        __syncthreads();
        // layer1 FFMA -> t1 (tf32-rounded fp32, stride 68)
        #pragma unroll
        for (int it = 0; it < 4; it++) {
            int s = tid + it * 512;
            int r = s >> 5, cp = s & 31, c = cp * 2;
            float v0 = b1s[c], v1 = b1s[c + 1];
            #pragma unroll
            for (int f = 0; f < 5; f++) {
                float xf = xs[r * 6 + f];
                v0 += xf * w1s[f * 64 + c];
                v1 += xf * w1s[f * 64 + c + 1];
            }
            float2 o;
            o.x = to_tf32(fmaxf(v0, 0.f));
            o.y = to_tf32(fmaxf(v1, 0.f));
            *(float2*)(smf + O_T1 + r * 68 + c) = o;
        }
        __syncthreads();
        {   // layer2 tf32: t2 = relu(t1 @ pW2 + b2)
            float acc[4][4];
            mma_block_t32<64, 128, 64>(sb + O_T1 * 4, sb + O_B2 * 4, wid, lane, acc);
            epi_smem_t32<128, 64>(acc, b2, smf + O_T2, wid, lane);
        }
        __syncthreads();
        {   // layer3 tf32: h0 = t2 @ pW3 + b3 -> bf16 + tf32-fp32 global
            float acc[4][4];
            mma_block_t32<128, 128, 64>(sb + O_T2 * 4, sb + O_B3 * 4, wid, lane, acc);
            const int wr = wid / 4, wc = wid % 4;
            const int mbase = wr * 16, nbase = wc * 32;
            const int g = lane >> 2, t = lane & 3;
            #pragma unroll
            for (int half = 0; half < 2; half++) {
                int r = mbase + g + half * 8;
                int rg = m0 + r;
                if (rg >= N) continue;
                #pragma unroll
                for (int nt = 0; nt < 4; nt++) {
                    int col = nbase + nt * 8 + 2 * t;
                    float ox = acc[nt][half * 2 + 0] + b3[col];
                    float oy = acc[nt][half * 2 + 1] + b3[col + 1];
                    ((uint32_t*)H0h)[((size_t)rg * 128 + col) >> 1] = pack_bf16(ox, oy);
                    float2 f; f.x = to_tf32(ox); f.y = to_tf32(oy);
                    *(float2*)(H0f + (size_t)rg * 128 + col) = f;
                }
            }
        }
    }
}

// ================= qk projection: h0h -> [q fp32 | k bf16], bf16 1-term =================
__global__ void __launch_bounds__(512, 1)
gemm_qk(const __nv_bfloat16* __restrict__ Ahg,
        const __nv_bfloat16* __restrict__ Bth,
        const float* __restrict__ bias,
        float* __restrict__ Q, __nv_bfloat16* __restrict__ Kb, int M)
{
    extern __shared__ __nv_bfloat16 sm[];
    constexpr int O_BH = 0;                    // [256][136]
    constexpr int O_AH = 34816;                // [64][136]
    const int tid = threadIdx.x, wid = tid >> 5, lane = tid & 31;
    const uint32_t sb = smem_u32(sm);

    for (int s = tid; s < 256 * 16; s += 512) {
        int r = s >> 4, c = s & 15;
        ((uint4*)(sm + O_BH + r * 136))[c] = ((const uint4*)(Bth + r * 128))[c];
    }

    const int ntiles = (M + 63) / 64;
    for (int tile = blockIdx.x; tile < ntiles; tile += gridDim.x) {
        const int m0 = tile * 64;
        __syncthreads();
        #pragma unroll
        for (int it = 0; it < 2; it++) {
            int s = tid + it * 512;
            int r = s >> 4, c = s & 15;
            int rg = m0 + r; if (rg > M - 1) rg = M - 1;
            ((uint4*)(sm + O_AH + r * 136))[c] = ((const uint4*)(Ahg + (size_t)rg * 128))[c];
        }
        __syncthreads();
        float acc[8][4];
        mma_block_b16<128, 256, 64>(sb + O_AH * 2, sb + O_BH * 2, wid, lane, acc);
        const int wr = wid / 8, wc = wid % 8;
        const int mbase = wr * 32, nbase = wc * 32;
        const int g = lane >> 2, t = lane & 3;
        #pragma unroll
        for (int mt = 0; mt < 2; mt++)
            #pragma unroll
            for (int half = 0; half < 2; half++) {
                int r = mbase + mt * 16 + g + half * 8;
                int rg = m0 + r;
                if (rg >= M) continue;
                #pragma unroll
                for (int nt = 0; nt < 4; nt++) {
                    int col = nbase + nt * 8 + 2 * t;
                    float ox = acc[mt * 4 + nt][half * 2 + 0] + bias[col];
                    float oy = acc[mt * 4 + nt][half * 2 + 1] + bias[col + 1];
                    if (col < 128) {
                        float2 o; o.x = ox; o.y = oy;
                        *(float2*)(Q + (size_t)rg * 256 + col) = o;
                    } else {
                        *(uint32_t*)(Kb + (size_t)rg * 128 + (col - 128)) = pack_bf16(ox, oy);
                    }
                }
            }
    }
}

// ================= sv projection: tf32 1-term (A from h0f) =================
__global__ void __launch_bounds__(512, 1)
gemm_sv_t32(const float* __restrict__ Af, const float* __restrict__ Btf,
            const float* __restrict__ bias,
            float* __restrict__ S, float* __restrict__ V, int M)
{
    extern __shared__ float smf[];
    constexpr int O_B = 0;                    // [256][132]
    constexpr int O_A = 256 * 132;            // [64][132]
    const int tid = threadIdx.x, wid = tid >> 5, lane = tid & 31;
    const uint32_t sb = smem_u32(smf);

    for (int s = tid; s < 256 * 32; s += 512) {
        int r = s >> 5, c = s & 31;
        ((float4*)(smf + O_B + r * 132))[c] = ((const float4*)(Btf + r * 128))[c];
    }

    const int ntiles = (M + 63) / 64;
    for (int tile = blockIdx.x; tile < ntiles; tile += gridDim.x) {
        const int m0 = tile * 64;
        __syncthreads();
        #pragma unroll
        for (int it = 0; it < 4; it++) {
            int s = tid + it * 512;
            int r = s >> 5, c = s & 31;
            int rg = m0 + r; if (rg > M - 1) rg = M - 1;
            ((float4*)(smf + O_A + r * 132))[c] = ((const float4*)(Af + (size_t)rg * 128))[c];
        }
        __syncthreads();
        float acc[8][4];
        mma_block_t32<128, 256, 64>(sb + O_A * 4, sb + O_B * 4, wid, lane, acc);
        const int wr = wid / 8, wc = wid % 8;
        const int mbase = wr * 32, nbase = wc * 32;
        const int g = lane >> 2, t = lane & 3;
        #pragma unroll
        for (int mt = 0; mt < 2; mt++)
            #pragma unroll
            for (int half = 0; half < 2; half++) {
                int r = mbase + mt * 16 + g + half * 8;
                int rg = m0 + r;
                if (rg >= M) continue;
                #pragma unroll
                for (int nt = 0; nt < 4; nt++) {
                    int col = nbase + nt * 8 + 2 * t;
                    float2 o;
                    o.x = acc[mt * 4 + nt][half * 2 + 0] + bias[col];
                    o.y = acc[mt * 4 + nt][half * 2 + 1] + bias[col + 1];
                    if (col < 128)
                        *(float2*)(S + (size_t)rg * 256 + 128 + col) = o;
                    else
                        *(float2*)(V + (size_t)rg * 128 + (col - 128)) = o;
                }
            }
    }
}

// ================= fused update MLP: tf32 1-term (+resid) =================
__global__ void __launch_bounds__(512, 1)
fused_update_t32(const float* __restrict__ H1,
                 const float* __restrict__ W1f, const float* __restrict__ W2f,
                 const float* __restrict__ W3f,
                 const float* __restrict__ ub1, const float* __restrict__ ub2,
                 const float* __restrict__ ub3, float* __restrict__ out, int N)
{
    extern __shared__ float smf[];
    constexpr int O_W1 = 0;
    constexpr int O_W2 = 8448;
    constexpr int O_W3 = 17152;
    constexpr int O_H1 = 34048;
    constexpr int O_T1 = 42496;
    constexpr int O_T2 = 46848;
    const int tid = threadIdx.x, wid = tid >> 5, lane = tid & 31;
    const uint32_t sb = smem_u32(smf);

    for (int s = tid; s < 64 * 32; s += 512) {
        int r = s >> 5, c = s & 31;
        ((float4*)(smf + O_W1 + r * 132))[c] = ((const float4*)(W1f + r * 128))[c];
    }
    for (int s = tid; s < 128 * 16; s += 512) {
        int r = s >> 4, c = s & 15;
        ((float4*)(smf + O_W2 + r * 68))[c] = ((const float4*)(W2f + r * 64))[c];
    }
    for (int s = tid; s < 128 * 32; s += 512) {
        int r = s >> 5, c = s & 31;
        ((float4*)(smf + O_W3 + r * 132))[c] = ((const float4*)(W3f + r * 128))[c];
    }

    const int ntiles = (N + 63) / 64;
    for (int tile = blockIdx.x; tile < ntiles; tile += gridDim.x) {
        const int m0 = tile * 64;
        __syncthreads();
        #pragma unroll
        for (int it = 0; it < 4; it++) {
            int s = tid + it * 512;
            int r = s >> 5, c = s & 31;
            int rg = m0 + r; if (rg > N - 1) rg = N - 1;
            float4 v = ((const float4*)(H1 + (size_t)rg * 128))[c];
            v.x = to_tf32(v.x); v.y = to_tf32(v.y);
            v.z = to_tf32(v.z); v.w = to_tf32(v.w);
            ((float4*)(smf + O_H1 + r * 132))[c] = v;
        }
        __syncthreads();
        {
            float acc[2][4];
            mma_block_t32<128, 64, 64>(sb + O_H1 * 4, sb + O_W1 * 4, wid, lane, acc);
            epi_smem_t32<64, 64>(acc, ub1, smf + O_T1, wid, lane);
        }
        __syncthreads();
        {
            float acc[4][4];
            mma_block_t32<64, 128, 64>(sb + O_T1 * 4, sb + O_W2 * 4, wid, lane, acc);
            epi_smem_t32<128, 64>(acc, ub2, smf + O_T2, wid, lane);
        }
        __syncthreads();
        {
            float acc[4][4];
            mma_block_t32<128, 128, 64>(sb + O_T2 * 4, sb + O_W3 * 4, wid, lane, acc);
            const int wr = wid / 4, wc = wid % 4;
            const int mbase = wr * 16, nbase = wc * 32;
            const int g = lane >> 2, t = lane & 3;
            #pragma unroll
            for (int half = 0; half < 2; half++) {
                int r = mbase + g + half * 8;
                int rg = m0 + r;
                if (rg >= N) continue;
                #pragma unroll
                for (int nt = 0; nt < 4; nt++) {
                    int col = nbase + nt * 8 + 2 * t;
                    float2 rv = *(const float2*)(H1 + (size_t)rg * 128 + col);
                    float2 o;
                    o.x = acc[nt][half * 2 + 0] + ub3[col] + rv.x;
                    o.y = acc[nt][half * 2 + 1] + ub3[col + 1] + rv.y;
                    *(float2*)(out + (size_t)rg * 128 + col) = o;
                }
            }
        }
    }
}

// ---------------- transpose weights ----------------
// z: 0=pW2 1=pW3 2=qW 3=kW 4=sW 5=vW 6=uW1 7=uW2 8=uW3
// bf16 hi for z=2,3 (qk); tf32 fp32 for z=0,1,4..8 at slots {0,1,-, -,2,3,4,5,6}
__global__ void transpose_all(const float* s0, const float* s1, const float* s2,
                              const float* s3, const float* s4, const float* s5,
                              const float* s6, const float* s7, const float* s8)
{
    const int Ks[9] = {64, 128, 128, 128, 128, 128, 128, 64, 128};
    const int Ns[9] = {128, 128, 128, 128, 128, 128, 64, 128, 128};
    const int Tf[9] = {0, 1, -1, -1, 2, 3, 4, 5, 6};
    const float* srcs[9] = {s0, s1, s2, s3, s4, s5, s6, s7, s8};
    int z = blockIdx.z;
    const float* src = srcs[z];
    __nv_bfloat16* dh = g_wth + z * 16384;
    float* df = (Tf[z] >= 0) ? (g_wtf + Tf[z] * 16384) : nullptr;
    int K = Ks[z], Nc = Ns[z];
    __shared__ float tile[32][33];
    int bx = blockIdx.x * 32, by = blockIdx.y * 32;
    int tx = threadIdx.x, ty = threadIdx.y;
    #pragma unroll
    for (int i = 0; i < 32; i += 8) {
        int k = by + ty + i, n = bx + tx;
        if (k < K && n < Nc) tile[ty + i][tx] = src[(long)k * Nc + n];
    }
    __syncthreads();
    #pragma unroll
    for (int i = 0; i < 32; i += 8) {
        int n = bx + ty + i, k = by + tx;
        if (n < Nc && k < K) {
            float v = tile[tx][ty + i];
            dh[(long)n * K + k] = __float2bfloat16(v);
            if (df) df[(long)n * K + k] = to_tf32(v);
        }
    }
}

__global__ void concat_bias(const float* qb, const float* kb,
                            const float* sb, const float* vb)
{
    int i = threadIdx.x;
    float v = (i < 128) ? qb[i] : (i < 256) ? kb[i - 128]
            : (i < 384) ? sb[i - 256] : vb[i - 384];
    g_bcat[i] = v;
}

// ---------------- CSR build ----------------
__global__ void zero_cnt_kernel(int N)
{
    int i = blockIdx.x * blockDim.x + threadIdx.x;
    if (i < N) g_cnt[i] = 0;
}
__global__ void hist_kernel(const int* __restrict__ dst, int E)
{
    int e = blockIdx.x * blockDim.x + threadIdx.x;
    if (e < E) g_pos[e] = atomicAdd(&g_cnt[dst[e]], 1);
}
__global__ void scan1_kernel(int N)
{
    __shared__ int sh[1024];
    int i = blockIdx.x * 1024 + threadIdx.x;
    int v = (i < N) ? g_cnt[i] : 0;
    sh[threadIdx.x] = v;
    __syncthreads();
    for (int d = 1; d < 1024; d <<= 1) {
        int tmp = (threadIdx.x >= d) ? sh[threadIdx.x - d] : 0;
        __syncthreads();
        sh[threadIdx.x] += tmp;
        __syncthreads();
    }
    if (i < N) g_off[i] = sh[threadIdx.x] - v;
    if (threadIdx.x == 1023) g_bsum[blockIdx.x] = sh[1023];
}
__global__ void scan2_kernel(int nb)
{
    if (blockIdx.x == 0 && threadIdx.x == 0) {
        int run = 0;
        for (int i = 0; i < nb; i++) { int v = g_bsum[i]; g_bsum[i] = run; run += v; }
    }
}
__global__ void scan3_kernel(int N, int E)
{
    int i = blockIdx.x * blockDim.x + threadIdx.x;
    if (i < N) g_off[i] += g_bsum[i >> 10];
    if (i == 0) g_off[N] = E;
}
__global__ void scatter_kernel(const int* __restrict__ src, const int* __restrict__ dst, int E)
{
    int e = blockIdx.x * blockDim.x + threadIdx.x;
    if (e < E) g_esrc[g_off[dst[e]] + g_pos[e]] = src[e];
}

// ---------------- attention: one warp per destination node ----------------
__global__ void attn_kernel(int N)
{
    int gtid = blockIdx.x * blockDim.x + threadIdx.x;
    int n    = gtid >> 5;
    int lane = threadIdx.x & 31;
    if (n >= N) return;

    const float4* qs4 = reinterpret_cast<const float4*>(g_qs);
    const uint2*  kb2 = reinterpret_cast<const uint2*>(g_kb);
    const float4* v4  = reinterpret_cast<const float4*>(g_v);

    float4 ql = qs4[(long)n * 64 + lane];
    int e0 = g_off[n], e1 = g_off[n + 1];

    const float scale = 0.17677669529663687f;
    float s0 = 0.f, s1 = 0.f;
    float4 a0 = make_float4(0.f, 0.f, 0.f, 0.f);
    float4 a1 = make_float4(0.f, 0.f, 0.f, 0.f);

    int e = e0;
    for (; e + 2 <= e1; e += 2) {
        int src0 = __ldg(&g_esrc[e]);
        int src1 = __ldg(&g_esrc[e + 1]);
        uint2 kw0 = kb2[(long)src0 * 32 + lane];
        uint2 kw1 = kb2[(long)src1 * 32 + lane];
        float4 v0 = v4[(long)src0 * 32 + lane];
        float4 v1 = v4[(long)src1 * 32 + lane];
        float2 k0a = __bfloat1622float2(*reinterpret_cast<__nv_bfloat162*>(&kw0.x));
        float2 k0b = __bfloat1622float2(*reinterpret_cast<__nv_bfloat162*>(&kw0.y));
        float2 k1a = __bfloat1622float2(*reinterpret_cast<__nv_bfloat162*>(&kw1.x));
        float2 k1b = __bfloat1622float2(*reinterpret_cast<__nv_bfloat162*>(&kw1.y));
        float p0 = ql.x * k0a.x + ql.y * k0a.y + ql.z * k0b.x + ql.w * k0b.y;
        float p1 = ql.x * k1a.x + ql.y * k1a.y + ql.z * k1b.x + ql.w * k1b.y;
        p0 += __shfl_xor_sync(0xffffffffu, p0, 1);
        p1 += __shfl_xor_sync(0xffffffffu, p1, 1);
        p0 += __shfl_xor_sync(0xffffffffu, p0, 2);
        p1 += __shfl_xor_sync(0xffffffffu, p1, 2);
        p0 += __shfl_xor_sync(0xffffffffu, p0, 4);
        p1 += __shfl_xor_sync(0xffffffffu, p1, 4);
        float w0 = __expf(p0 * scale);
        float w1 = __expf(p1 * scale);
        s0 += w0; s1 += w1;
        a0.x += w0 * v0.x; a0.y += w0 * v0.y; a0.z += w0 * v0.z; a0.w += w0 * v0.w;
        a1.x += w1 * v1.x; a1.y += w1 * v1.y; a1.z += w1 * v1.z; a1.w += w1 * v1.w;
    }
    if (e < e1) {
        int src0 = __ldg(&g_esrc[e]);
        uint2 kw0 = kb2[(long)src0 * 32 + lane];
        float4 v0 = v4[(long)src0 * 32 + lane];
        float2 k0a = __bfloat1622float2(*reinterpret_cast<__nv_bfloat162*>(&kw0.x));
        float2 k0b = __bfloat1622float2(*reinterpret_cast<__nv_bfloat162*>(&kw0.y));
        float p0 = ql.x * k0a.x + ql.y * k0a.y + ql.z * k0b.x + ql.w * k0b.y;
        p0 += __shfl_xor_sync(0xffffffffu, p0, 1);
        p0 += __shfl_xor_sync(0xffffffffu, p0, 2);
        p0 += __shfl_xor_sync(0xffffffffu, p0, 4);
        float w0 = __expf(p0 * scale);
        s0 += w0;
        a0.x += w0 * v0.x; a0.y += w0 * v0.y; a0.z += w0 * v0.z; a0.w += w0 * v0.w;
    }
    float s = s0 + s1;
    float inv = (s > 0.f) ? (1.f / s) : 0.f;
    float4 sk = qs4[(long)n * 64 + 32 + lane];
    float4 o;
    o.x = (a0.x + a1.x) * inv + sk.x;
    o.y = (a0.y + a1.y) * inv + sk.y;
    o.z = (a0.z + a1.z) * inv + sk.z;
    o.w = (a0.w + a1.w) * inv + sk.w;
    ((float4*)g_h1f)[(long)n * 32 + lane] = o;
}

// ---------------- host ----------------
extern "C" void kernel_launch(void* const* d_in, const int* in_sizes, int n_in,
                              void* d_out, int out_size)
{
    const float* x    = (const float*)d_in[0];
    const int*   ei   = (const int*)  d_in[1];
    const float* pW1  = (const float*)d_in[2];
    const float* pb1  = (const float*)d_in[3];
    const float* pW2  = (const float*)d_in[4];
    const float* pb2  = (const float*)d_in[5];
    const float* pW3  = (const float*)d_in[6];
    const float* pb3  = (const float*)d_in[7];
    const float* uW1  = (const float*)d_in[8];
    const float* ub1  = (const float*)d_in[9];
    const float* uW2  = (const float*)d_in[10];
    const float* ub2  = (const float*)d_in[11];
    const float* uW3  = (const float*)d_in[12];
    const float* ub3  = (const float*)d_in[13];
    const float* qW   = (const float*)d_in[14];
    const float* qb   = (const float*)d_in[15];
    const float* kW   = (const float*)d_in[16];
    const float* kb   = (const float*)d_in[17];
    const float* vW   = (const float*)d_in[18];
    const float* vb   = (const float*)d_in[19];
    const float* sW   = (const float*)d_in[20];
    const float* sb   = (const float*)d_in[21];
    float* out = (float*)d_out;

    const int F = 5;
    const int N = in_sizes[0] / F;
    const int E = in_sizes[1] / 2;
    const int* src = ei;
    const int* dst = ei + E;

    __nv_bfloat16 *h0h, *wh, *kbuf;
    float *qs, *vbuf, *bc, *h0f, *h1f, *wf;
    cudaGetSymbolAddress((void**)&h0h,  g_h0h);
    cudaGetSymbolAddress((void**)&h0f,  g_h0f);
    cudaGetSymbolAddress((void**)&h1f,  g_h1f);
    cudaGetSymbolAddress((void**)&qs,   g_qs);
    cudaGetSymbolAddress((void**)&kbuf, g_kb);
    cudaGetSymbolAddress((void**)&vbuf, g_v);
    cudaGetSymbolAddress((void**)&bc,   g_bcat);
    cudaGetSymbolAddress((void**)&wh,   g_wth);
    cudaGetSymbolAddress((void**)&wf,   g_wtf);

    // ---- fork CSR build onto side stream ----
    cudaEventRecord(g_ev_fork, 0);
    cudaStreamWaitEvent(g_s2, g_ev_fork, 0);
    {
        int nb1024 = (N + 1023) / 1024;
        zero_cnt_kernel<<<(N + 255) / 256, 256, 0, g_s2>>>(N);
        hist_kernel<<<(E + 255) / 256, 256, 0, g_s2>>>(dst, E);
        scan1_kernel<<<nb1024, 1024, 0, g_s2>>>(N);
        scan2_kernel<<<1, 32, 0, g_s2>>>(nb1024);
        scan3_kernel<<<(N + 255) / 256, 256, 0, g_s2>>>(N, E);
        scatter_kernel<<<(E + 255) / 256, 256, 0, g_s2>>>(src, dst, E);
    }

    // ---- main chain ----
    {
        dim3 tgrid(4, 4, 9), tblk(32, 8);
        transpose_all<<<tgrid, tblk>>>(pW2, pW3, qW, kW, sW, vW, uW1, uW2, uW3);
        concat_bias<<<1, 512>>>(qb, kb, sb, vb);
    }
    {
        int smem = (38400 + 768) * 4;   // 156,672 B
        cudaFuncSetAttribute(fused_prep, cudaFuncAttributeMaxDynamicSharedMemorySize, smem);
        fused_prep<<<148, 512, smem>>>(x, pW1, pb1,
            wf + 0 * 16384, wf + 1 * 16384, pb2, pb3, h0h, h0f, N);
    }
    cudaEventRecord(g_ev_prep, 0);

    // qk (bf16 1-term) on side stream, overlapped with sv on main (R12 structure)
    cudaStreamWaitEvent(g_s2, g_ev_prep, 0);
    {
        int smemA = (256 * 136 + 64 * 136) * 2;   // 87,040 B
        cudaFuncSetAttribute(gemm_qk, cudaFuncAttributeMaxDynamicSharedMemorySize, smemA);
        gemm_qk<<<148, 512, smemA, g_s2>>>(h0h, wh + 2 * 16384, bc, qs, kbuf, N);
        cudaEventRecord(g_ev_join, g_s2);
    }
    {
        int smemB = (256 * 132 + 64 * 132) * 4;   // 168,960 B
        cudaFuncSetAttribute(gemm_sv_t32, cudaFuncAttributeMaxDynamicSharedMemorySize, smemB);
        gemm_sv_t32<<<148, 512, smemB>>>(h0f, wf + 2 * 16384, bc + 256, qs, vbuf, N);
    }

    cudaStreamWaitEvent(0, g_ev_join, 0);

    long tt = (long)N * 32;
    attn_kernel<<<(int)((tt + 255) / 256), 256>>>(N);

    {
        int smem = 55296 * 4;
        cudaFuncSetAttribute(fused_update_t32, cudaFuncAttributeMaxDynamicSharedMemorySize, smem);
        fused_update_t32<<<148, 512, smem>>>(h1f,
            wf + 4 * 16384, wf + 5 * 16384, wf + 6 * 16384,
            ub1, ub2, ub3, out, N);
    }
}

// round 15
// speedup vs baseline: 1.0908x; 1.0227x over previous
#include <cuda_runtime.h>
#include <cuda_bf16.h>
#include <cuda_fp16.h>
#include <cstdint>
#include <math.h>

#define MAXN 100000
#define MAXE 800000

// ---------------- device scratch ----------------
__device__ __nv_bfloat16 g_h0h[MAXN * 128];  // h0 bf16 (for qk)
__device__ float g_h0f[MAXN * 128];          // h0 tf32-rounded fp32 (for sv)
__device__ float g_h1f[MAXN * 128];          // h1 fp32 (attention out)
__device__ float g_qs[MAXN * 256];           // cols 0-127: q, 128-255: skip (fp32)
__device__ uint32_t g_kv[MAXN * 128];        // row: [k bf16 x128 (64w) | v fp16 x128 (64w)]
__device__ __nv_bfloat16 g_wth[9 * 128 * 128];
__device__ float g_wtf[7 * 128 * 128];       // tf32 fp32: 0=pW2 1=pW3 2,3=sW|vW 4=uW1 5=uW2 6=uW3
__device__ float g_bcat[512];                // [qb|kb|sb|vb]
__device__ int   g_cnt[MAXN];
__device__ int   g_off[MAXN + 1];
__device__ int   g_bsum[256];
__device__ int   g_pos[MAXE];
__device__ int   g_esrc[MAXE];

// ---------------- side stream ----------------
static cudaStream_t g_s2;
static cudaEvent_t  g_ev_fork, g_ev_prep, g_ev_join;
namespace {
struct StreamInit {
    StreamInit() {
        cudaStreamCreateWithFlags(&g_s2, cudaStreamNonBlocking);
        cudaEventCreateWithFlags(&g_ev_fork, cudaEventDisableTiming);
        cudaEventCreateWithFlags(&g_ev_prep, cudaEventDisableTiming);
        cudaEventCreateWithFlags(&g_ev_join, cudaEventDisableTiming);
    }
};
StreamInit g_stream_init;
}

__device__ __forceinline__ uint32_t smem_u32(const void* p) {
    uint32_t a;
    asm("{ .reg .u64 t; cvta.to.shared.u64 t, %1; cvt.u32.u64 %0, t; }" : "=r"(a) : "l"(p));
    return a;
}
__device__ __forceinline__ uint32_t pack_bf16(float a, float b) {
    __nv_bfloat16 ha = __float2bfloat16(a);
    __nv_bfloat16 hb = __float2bfloat16(b);
    uint16_t ua = *(uint16_t*)&ha, ub = *(uint16_t*)&hb;
    return (uint32_t)ua | ((uint32_t)ub << 16);
}
__device__ __forceinline__ float to_tf32(float x) {
    float y; asm("cvt.rna.tf32.f32 %0, %1;" : "=f"(y) : "f"(x)); return y;
}
__device__ __forceinline__ void mma_bf16(float c[4], const uint32_t a[4], const uint32_t b[2]) {
    asm volatile(
        "mma.sync.aligned.m16n8k16.row.col.f32.bf16.bf16.f32 "
        "{%0,%1,%2,%3}, {%4,%5,%6,%7}, {%8,%9}, {%0,%1,%2,%3};"
        : "+f"(c[0]), "+f"(c[1]), "+f"(c[2]), "+f"(c[3])
        : "r"(a[0]), "r"(a[1]), "r"(a[2]), "r"(a[3]), "r"(b[0]), "r"(b[1]));
}
__device__ __forceinline__ void mma_tf32(float c[4], const uint32_t a[4], const uint32_t b[2]) {
    asm volatile(
        "mma.sync.aligned.m16n8k8.row.col.f32.tf32.tf32.f32 "
        "{%0,%1,%2,%3}, {%4,%5,%6,%7}, {%8,%9}, {%0,%1,%2,%3};"
        : "+f"(c[0]), "+f"(c[1]), "+f"(c[2]), "+f"(c[3])
        : "r"(a[0]), "r"(a[1]), "r"(a[2]), "r"(a[3]), "r"(b[0]), "r"(b[1]));
}
__device__ __forceinline__ void ldsm_x4(uint32_t* r, uint32_t addr) {
    asm volatile("ldmatrix.sync.aligned.m8n8.x4.shared.b16 {%0,%1,%2,%3}, [%4];"
        : "=r"(r[0]), "=r"(r[1]), "=r"(r[2]), "=r"(r[3]) : "r"(addr));
}

// ============ bf16 1-term MMA block, bf16 SMEM, stride K+8 ============
template <int K, int NOUT, int TM>
__device__ __forceinline__ void mma_block_b16(
    uint32_t sAh, uint32_t sBh, int wid, int lane, float acc[][4])
{
    constexpr int WC = (NOUT == 256) ? 8 : 4;
    constexpr int WR = 16 / WC;
    constexpr int MT = TM / (WR * 16);
    constexpr int NT = NOUT / (8 * WC);
    constexpr int NB = NT / 2;
    constexpr int LDSK = K + 8;
    const int wr = wid / WC, wc = wid % WC;
    const int mbase = wr * (MT * 16);
    const int nbase = wc * (NT * 8);
    const int lrow = lane & 15, lhalf = lane >> 4;
    const int seg = lane >> 3;
    const int brow = ((seg >> 1) << 3) + (lane & 7);
    const int bk = (seg & 1) * 8;

    #pragma unroll
    for (int i = 0; i < MT * NT; i++)
        #pragma unroll
        for (int j = 0; j < 4; j++) acc[i][j] = 0.f;

    uint32_t aoffs[MT], boffs[NB];
    #pragma unroll
    for (int mt = 0; mt < MT; mt++)
        aoffs[mt] = ((mbase + mt * 16 + lrow) * LDSK + 8 * lhalf) * 2;
    #pragma unroll
    for (int p = 0; p < NB; p++)
        boffs[p] = ((nbase + p * 16 + brow) * LDSK + bk) * 2;

    #pragma unroll
    for (int k0 = 0; k0 < K; k0 += 16) {
        const uint32_t koff = k0 * 2;
        uint32_t bh[NB][4];
        #pragma unroll
        for (int p = 0; p < NB; p++)
            ldsm_x4(bh[p], sBh + boffs[p] + koff);
        #pragma unroll
        for (int mt = 0; mt < MT; mt++) {
            uint32_t ah[4];
            ldsm_x4(ah, sAh + aoffs[mt] + koff);
            #pragma unroll
            for (int nt = 0; nt < NT; nt++)
                mma_bf16(acc[mt * NT + nt], ah, &bh[nt >> 1][(nt & 1) * 2]);
        }
    }
}

// ============ tf32 1-term MMA block, fp32 SMEM tiles, stride K+4 floats ============
template <int K, int NOUT, int TM>
__device__ __forceinline__ void mma_block_t32(
    uint32_t sA, uint32_t sB, int wid, int lane, float acc[][4])
{
    constexpr int WC = (NOUT == 256) ? 8 : 4;
    constexpr int WR = 16 / WC;
    constexpr int MT = TM / (WR * 16);
    constexpr int NT = NOUT / (8 * WC);
    constexpr int NG = NT / 2;
    constexpr int LDSK = K + 4;
    const int wr = wid / WC, wc = wid % WC;
    const int mbase = wr * (MT * 16);
    const int nbase = wc * (NT * 8);

    #pragma unroll
    for (int i = 0; i < MT * NT; i++)
        #pragma unroll
        for (int j = 0; j < 4; j++) acc[i][j] = 0.f;

    const int arow = ((lane >> 3) & 1) * 8 + (lane & 7);
    const int akof = (lane >> 4) * 4;
    const int brow = ((lane >> 4) & 1) * 8 + (lane & 7);
    const int bkof = ((lane >> 3) & 1) * 4;

    uint32_t aaddr[MT], baddr[NG];
    #pragma unroll
    for (int mt = 0; mt < MT; mt++)
        aaddr[mt] = sA + ((mbase + mt * 16 + arow) * LDSK + akof) * 4;
    #pragma unroll
    for (int gp = 0; gp < NG; gp++)
        baddr[gp] = sB + ((nbase + gp * 16 + brow) * LDSK + bkof) * 4;

    #pragma unroll
    for (int k0 = 0; k0 < K; k0 += 8) {
        const uint32_t koff = k0 * 4;
        uint32_t bf[NG][4];
        #pragma unroll
        for (int gp = 0; gp < NG; gp++)
            ldsm_x4(bf[gp], baddr[gp] + koff);
        #pragma unroll
        for (int mt = 0; mt < MT; mt++) {
            uint32_t af[4];
            ldsm_x4(af, aaddr[mt] + koff);
            #pragma unroll
            for (int nt = 0; nt < NT; nt++)
                mma_tf32(acc[mt * NT + nt], af, &bf[nt >> 1][(nt & 1) * 2]);
        }
    }
}

// ---- tf32 epilogue into fp32 SMEM tile (stride NOUT+4), relu + tf32 round ----
template <int NOUT, int TM>
__device__ __forceinline__ void epi_smem_t32(
    float acc[][4], const float* __restrict__ bias,
    float* D, int wid, int lane)
{
    constexpr int WC = (NOUT == 256) ? 8 : 4;
    constexpr int WR = 16 / WC;
    constexpr int MT = TM / (WR * 16);
    constexpr int NT = NOUT / (8 * WC);
    constexpr int LDSO = NOUT + 4;
    const int wr = wid / WC, wc = wid % WC;
    const int mbase = wr * (MT * 16);
    const int nbase = wc * (NT * 8);
    const int g = lane >> 2, t = lane & 3;
    #pragma unroll
    for (int mt = 0; mt < MT; mt++)
        #pragma unroll
        for (int half = 0; half < 2; half++) {
            int r = mbase + mt * 16 + g + half * 8;
            #pragma unroll
            for (int nt = 0; nt < NT; nt++) {
                int col = nbase + nt * 8 + 2 * t;
                float ox = fmaxf(acc[mt * NT + nt][half * 2 + 0] + bias[col], 0.f);
                float oy = fmaxf(acc[mt * NT + nt][half * 2 + 1] + bias[col + 1], 0.f);
                float2 o; o.x = to_tf32(ox); o.y = to_tf32(oy);
                *(float2*)(D + r * LDSO + col) = o;
            }
        }
}

// ================= fused prep MLP: x(5) ->FFMA 64 ->tf32 128 ->tf32 128 =================
__global__ void __launch_bounds__(512, 1)
fused_prep(const float* __restrict__ x, const float* __restrict__ W1,
           const float* __restrict__ b1,
           const float* __restrict__ B2f, const float* __restrict__ B3f,
           const float* __restrict__ b2, const float* __restrict__ b3,
           __nv_bfloat16* __restrict__ H0h, float* __restrict__ H0f, int N)
{
    extern __shared__ float smf[];
    constexpr int O_B2 = 0;
    constexpr int O_B3 = 8704;
    constexpr int O_T1 = 25600;
    constexpr int O_T2 = 29952;
    constexpr int O_XW = 38400;
    float* xs  = smf + O_XW;
    float* w1s = xs + 384;
    float* b1s = w1s + 320;

    const int tid = threadIdx.x, wid = tid >> 5, lane = tid & 31;
    const uint32_t sb = smem_u32(smf);

    for (int s = tid; s < 128 * 16; s += 512) {
        int r = s >> 4, c = s & 15;
        ((float4*)(smf + O_B2 + r * 68))[c] = ((const float4*)(B2f + r * 64))[c];
    }
    for (int s = tid; s < 128 * 32; s += 512) {
        int r = s >> 5, c = s & 31;
        ((float4*)(smf + O_B3 + r * 132))[c] = ((const float4*)(B3f + r * 128))[c];
    }
    if (tid < 320) w1s[tid] = W1[tid];
    if (tid < 64)  b1s[tid] = b1[tid];

    const int ntiles = (N + 63) / 64;
    for (int tile = blockIdx.x; tile < ntiles; tile += gridDim.x) {
        const int m0 = tile * 64;
        __syncthreads();
        if (tid < 320) {
            int r = tid / 5, c = tid % 5;
            int rg = m0 + r; if (rg > N - 1) rg = N - 1;
            xs[r * 6 + c] = x[(size_t)rg * 5 + c];
        }
        __syncthreads();
        #pragma unroll
        for (int it = 0; it < 4; it++) {
            int s = tid + it * 512;
            int r = s >> 5, cp = s & 31, c = cp * 2;
            float v0 = b1s[c], v1 = b1s[c + 1];
            #pragma unroll
            for (int f = 0; f < 5; f++) {
                float xf = xs[r * 6 + f];
                v0 += xf * w1s[f * 64 + c];
                v1 += xf * w1s[f * 64 + c + 1];
            }
            float2 o;
            o.x = to_tf32(fmaxf(v0, 0.f));
            o.y = to_tf32(fmaxf(v1, 0.f));
            *(float2*)(smf + O_T1 + r * 68 + c) = o;
        }
        __syncthreads();
        {
            float acc[4][4];
            mma_block_t32<64, 128, 64>(sb + O_T1 * 4, sb + O_B2 * 4, wid, lane, acc);
            epi_smem_t32<128, 64>(acc, b2, smf + O_T2, wid, lane);
        }
        __syncthreads();
        {
            float acc[4][4];
            mma_block_t32<128, 128, 64>(sb + O_T2 * 4, sb + O_B3 * 4, wid, lane, acc);
            const int wr = wid / 4, wc = wid % 4;
            const int mbase = wr * 16, nbase = wc * 32;
            const int g = lane >> 2, t = lane & 3;
            #pragma unroll
            for (int half = 0; half < 2; half++) {
                int r = mbase + g + half * 8;
                int rg = m0 + r;
                if (rg >= N) continue;
                #pragma unroll
                for (int nt = 0; nt < 4; nt++) {
                    int col = nbase + nt * 8 + 2 * t;
                    float ox = acc[nt][half * 2 + 0] + b3[col];
                    float oy = acc[nt][half * 2 + 1] + b3[col + 1];
                    ((uint32_t*)H0h)[((size_t)rg * 128 + col) >> 1] = pack_bf16(ox, oy);
                    float2 f; f.x = to_tf32(ox); f.y = to_tf32(oy);
                    *(float2*)(H0f + (size_t)rg * 128 + col) = f;
                }
            }
        }
    }
}

// ================= qk projection: h0h -> [q fp32 | k bf16 into kv], bf16 1-term =========
__global__ void __launch_bounds__(512, 1)
gemm_qk(const __nv_bfloat16* __restrict__ Ahg,
        const __nv_bfloat16* __restrict__ Bth,
        const float* __restrict__ bias,
        float* __restrict__ Q, uint32_t* __restrict__ KV, int M)
{
    extern __shared__ __nv_bfloat16 sm[];
    constexpr int O_BH = 0;
    constexpr int O_AH = 34816;
    const int tid = threadIdx.x, wid = tid >> 5, lane = tid & 31;
    const uint32_t sb = smem_u32(sm);

    for (int s = tid; s < 256 * 16; s += 512) {
        int r = s >> 4, c = s & 15;
        ((uint4*)(sm + O_BH + r * 136))[c] = ((const uint4*)(Bth + r * 128))[c];
    }

    const int ntiles = (M + 63) / 64;
    for (int tile = blockIdx.x; tile < ntiles; tile += gridDim.x) {
        const int m0 = tile * 64;
        __syncthreads();
        #pragma unroll
        for (int it = 0; it < 2; it++) {
            int s = tid + it * 512;
            int r = s >> 4, c = s & 15;
            int rg = m0 + r; if (rg > M - 1) rg = M - 1;
            ((uint4*)(sm + O_AH + r * 136))[c] = ((const uint4*)(Ahg + (size_t)rg * 128))[c];
        }
        __syncthreads();
        float acc[8][4];
        mma_block_b16<128, 256, 64>(sb + O_AH * 2, sb + O_BH * 2, wid, lane, acc);
        const int wr = wid / 8, wc = wid % 8;
        const int mbase = wr * 32, nbase = wc * 32;
        const int g = lane >> 2, t = lane & 3;
        #pragma unroll
        for (int mt = 0; mt < 2; mt++)
            #pragma unroll
            for (int half = 0; half < 2; half++) {
                int r = mbase + mt * 16 + g + half * 8;
                int rg = m0 + r;
                if (rg >= M) continue;
                #pragma unroll
                for (int nt = 0; nt < 4; nt++) {
                    int col = nbase + nt * 8 + 2 * t;
                    float ox = acc[mt * 4 + nt][half * 2 + 0] + bias[col];
                    float oy = acc[mt * 4 + nt][half * 2 + 1] + bias[col + 1];
                    if (col < 128) {
                        float2 o; o.x = ox; o.y = oy;
                        *(float2*)(Q + (size_t)rg * 256 + col) = o;
                    } else {
                        KV[(size_t)rg * 128 + ((col - 128) >> 1)] = pack_bf16(ox, oy);
                    }
                }
            }
    }
}

// ================= sv projection: tf32 1-term; skip fp32, v fp16 into kv ==========
__global__ void __launch_bounds__(512, 1)
gemm_sv_t32(const float* __restrict__ Af, const float* __restrict__ Btf,
            const float* __restrict__ bias,
            float* __restrict__ S, uint32_t* __restrict__ KV, int M)
{
    extern __shared__ float smf[];
    constexpr int O_B = 0;
    constexpr int O_A = 256 * 132;
    const int tid = threadIdx.x, wid = tid >> 5, lane = tid & 31;
    const uint32_t sb = smem_u32(smf);

    for (int s = tid; s < 256 * 32; s += 512) {
        int r = s >> 5, c = s & 31;
        ((float4*)(smf + O_B + r * 132))[c] = ((const float4*)(Btf + r * 128))[c];
    }

    const int ntiles = (M + 63) / 64;
    for (int tile = blockIdx.x; tile < ntiles; tile += gridDim.x) {
        const int m0 = tile * 64;
        __syncthreads();
        #pragma unroll
        for (int it = 0; it < 4; it++) {
            int s = tid + it * 512;
            int r = s >> 5, c = s & 31;
            int rg = m0 + r; if (rg > M - 1) rg = M - 1;
            ((float4*)(smf + O_A + r * 132))[c] = ((const float4*)(Af + (size_t)rg * 128))[c];
        }
        __syncthreads();
        float acc[8][4];
        mma_block_t32<128, 256, 64>(sb + O_A * 4, sb + O_B * 4, wid, lane, acc);
        const int wr = wid / 8, wc = wid % 8;
        const int mbase = wr * 32, nbase = wc * 32;
        const int g = lane >> 2, t = lane & 3;
        #pragma unroll
        for (int mt = 0; mt < 2; mt++)
            #pragma unroll
            for (int half = 0; half < 2; half++) {
                int r = mbase + mt * 16 + g + half * 8;
                int rg = m0 + r;
                if (rg >= M) continue;
                #pragma unroll
                for (int nt = 0; nt < 4; nt++) {
                    int col = nbase + nt * 8 + 2 * t;
                    float ox = acc[mt * 4 + nt][half * 2 + 0] + bias[col];
                    float oy = acc[mt * 4 + nt][half * 2 + 1] + bias[col + 1];
                    if (col < 128) {
                        float2 o; o.x = ox; o.y = oy;
                        *(float2*)(S + (size_t)rg * 256 + 128 + col) = o;
                    } else {
                        __half2 h2 = __floats2half2_rn(ox, oy);
                        KV[(size_t)rg * 128 + 64 + ((col - 128) >> 1)] = *(uint32_t*)&h2;
                    }
                }
            }
    }
}

// ================= fused update MLP: tf32 1-term (+resid) =================
__global__ void __launch_bounds__(512, 1)
fused_update_t32(const float* __restrict__ H1,
                 const float* __restrict__ W1f, const float* __restrict__ W2f,
                 const float* __restrict__ W3f,
                 const float* __restrict__ ub1, const float* __restrict__ ub2,
                 const float* __restrict__ ub3, float* __restrict__ out, int N)
{
    extern __shared__ float smf[];
    constexpr int O_W1 = 0;
    constexpr int O_W2 = 8448;
    constexpr int O_W3 = 17152;
    constexpr int O_H1 = 34048;
    constexpr int O_T1 = 42496;
    constexpr int O_T2 = 46848;
    const int tid = threadIdx.x, wid = tid >> 5, lane = tid & 31;
    const uint32_t sb = smem_u32(smf);

    for (int s = tid; s < 64 * 32; s += 512) {
        int r = s >> 5, c = s & 31;
        ((float4*)(smf + O_W1 + r * 132))[c] = ((const float4*)(W1f + r * 128))[c];
    }
    for (int s = tid; s < 128 * 16; s += 512) {
        int r = s >> 4, c = s & 15;
        ((float4*)(smf + O_W2 + r * 68))[c] = ((const float4*)(W2f + r * 64))[c];
    }
    for (int s = tid; s < 128 * 32; s += 512) {
        int r = s >> 5, c = s & 31;
        ((float4*)(smf + O_W3 + r * 132))[c] = ((const float4*)(W3f + r * 128))[c];
    }

    const int ntiles = (N + 63) / 64;
    for (int tile = blockIdx.x; tile < ntiles; tile += gridDim.x) {
        const int m0 = tile * 64;
        __syncthreads();
        #pragma unroll
        for (int it = 0; it < 4; it++) {
            int s = tid + it * 512;
            int r = s >> 5, c = s & 31;
            int rg = m0 + r; if (rg > N - 1) rg = N - 1;
            float4 v = ((const float4*)(H1 + (size_t)rg * 128))[c];
            v.x = to_tf32(v.x); v.y = to_tf32(v.y);
            v.z = to_tf32(v.z); v.w = to_tf32(v.w);
            ((float4*)(smf + O_H1 + r * 132))[c] = v;
        }
        __syncthreads();
        {
            float acc[2][4];
            mma_block_t32<128, 64, 64>(sb + O_H1 * 4, sb + O_W1 * 4, wid, lane, acc);
            epi_smem_t32<64, 64>(acc, ub1, smf + O_T1, wid, lane);
        }
        __syncthreads();
        {
            float acc[4][4];
            mma_block_t32<64, 128, 64>(sb + O_T1 * 4, sb + O_W2 * 4, wid, lane, acc);
            epi_smem_t32<128, 64>(acc, ub2, smf + O_T2, wid, lane);
        }
        __syncthreads();
        {
            float acc[4][4];
            mma_block_t32<128, 128, 64>(sb + O_T2 * 4, sb + O_W3 * 4, wid, lane, acc);
            const int wr = wid / 4, wc = wid % 4;
            const int mbase = wr * 16, nbase = wc * 32;
            const int g = lane >> 2, t = lane & 3;
            #pragma unroll
            for (int half = 0; half < 2; half++) {
                int r = mbase + g + half * 8;
                int rg = m0 + r;
                if (rg >= N) continue;
                #pragma unroll
                for (int nt = 0; nt < 4; nt++) {
                    int col = nbase + nt * 8 + 2 * t;
                    float2 rv = *(const float2*)(H1 + (size_t)rg * 128 + col);
                    float2 o;
                    o.x = acc[nt][half * 2 + 0] + ub3[col] + rv.x;
                    o.y = acc[nt][half * 2 + 1] + ub3[col + 1] + rv.y;
                    *(float2*)(out + (size_t)rg * 128 + col) = o;
                }
            }
        }
    }
}

// ---------------- transpose weights ----------------
// z: 0=pW2 1=pW3 2=qW 3=kW 4=sW 5=vW 6=uW1 7=uW2 8=uW3
__global__ void transpose_all(const float* s0, const float* s1, const float* s2,
                              const float* s3, const float* s4, const float* s5,
                              const float* s6, const float* s7, const float* s8)
{
    const int Ks[9] = {64, 128, 128, 128, 128, 128, 128, 64, 128};
    const int Ns[9] = {128, 128, 128, 128, 128, 128, 64, 128, 128};
    const int Tf[9] = {0, 1, -1, -1, 2, 3, 4, 5, 6};
    const float* srcs[9] = {s0, s1, s2, s3, s4, s5, s6, s7, s8};
    int z = blockIdx.z;
    const float* src = srcs[z];
    __nv_bfloat16* dh = g_wth + z * 16384;
    float* df = (Tf[z] >= 0) ? (g_wtf + Tf[z] * 16384) : nullptr;
    int K = Ks[z], Nc = Ns[z];
    __shared__ float tile[32][33];
    int bx = blockIdx.x * 32, by = blockIdx.y * 32;
    int tx = threadIdx.x, ty = threadIdx.y;
    #pragma unroll
    for (int i = 0; i < 32; i += 8) {
        int k = by + ty + i, n = bx + tx;
        if (k < K && n < Nc) tile[ty + i][tx] = src[(long)k * Nc + n];
    }
    __syncthreads();
    #pragma unroll
    for (int i = 0; i < 32; i += 8) {
        int n = bx + ty + i, k = by + tx;
        if (n < Nc && k < K) {
            float v = tile[tx][ty + i];
            dh[(long)n * K + k] = __float2bfloat16(v);
            if (df) df[(long)n * K + k] = to_tf32(v);
        }
    }
}

__global__ void concat_bias(const float* qb, const float* kb,
                            const float* sb, const float* vb)
{
    int i = threadIdx.x;
    float v = (i < 128) ? qb[i] : (i < 256) ? kb[i - 128]
            : (i < 384) ? sb[i - 256] : vb[i - 384];
    g_bcat[i] = v;
}

// ---------------- CSR build ----------------
__global__ void zero_cnt_kernel(int N)
{
    int i = blockIdx.x * blockDim.x + threadIdx.x;
    if (i < N) g_cnt[i] = 0;
}
__global__ void hist_kernel(const int* __restrict__ dst, int E)
{
    int e = blockIdx.x * blockDim.x + threadIdx.x;
    if (e < E) g_pos[e] = atomicAdd(&g_cnt[dst[e]], 1);
}
__global__ void scan1_kernel(int N)
{
    __shared__ int sh[1024];
    int i = blockIdx.x * 1024 + threadIdx.x;
    int v = (i < N) ? g_cnt[i] : 0;
    sh[threadIdx.x] = v;
    __syncthreads();
    for (int d = 1; d < 1024; d <<= 1) {
        int tmp = (threadIdx.x >= d) ? sh[threadIdx.x - d] : 0;
        __syncthreads();
        sh[threadIdx.x] += tmp;
        __syncthreads();
    }
    if (i < N) g_off[i] = sh[threadIdx.x] - v;
    if (threadIdx.x == 1023) g_bsum[blockIdx.x] = sh[1023];
}
__global__ void scan2_kernel(int nb)
{
    if (blockIdx.x == 0 && threadIdx.x == 0) {
        int run = 0;
        for (int i = 0; i < nb; i++) { int v = g_bsum[i]; g_bsum[i] = run; run += v; }
    }
}
__global__ void scan3_kernel(int N, int E)
{
    int i = blockIdx.x * blockDim.x + threadIdx.x;
    if (i < N) g_off[i] += g_bsum[i >> 10];
    if (i == 0) g_off[N] = E;
}
__global__ void scatter_kernel(const int* __restrict__ src, const int* __restrict__ dst, int E)
{
    int e = blockIdx.x * blockDim.x + threadIdx.x;
    if (e < E) g_esrc[g_off[dst[e]] + g_pos[e]] = src[e];
}

// ---------------- attention: one warp per destination node ----------------
// kv row: [k bf16 x128 -> uint2 idx 0..31 | v fp16 x128 -> uint2 idx 32..63]
__global__ void attn_kernel(int N)
{
    int gtid = blockIdx.x * blockDim.x + threadIdx.x;
    int n    = gtid >> 5;
    int lane = threadIdx.x & 31;
    if (n >= N) return;

    const float4* qs4 = reinterpret_cast<const float4*>(g_qs);
    const uint2*  kv2 = reinterpret_cast<const uint2*>(g_kv);

    float4 ql = qs4[(long)n * 64 + lane];
    int e0 = g_off[n], e1 = g_off[n + 1];

    const float scale = 0.17677669529663687f;
    float s0 = 0.f, s1 = 0.f;
    float4 a0 = make_float4(0.f, 0.f, 0.f, 0.f);
    float4 a1 = make_float4(0.f, 0.f, 0.f, 0.f);

    int e = e0;
    for (; e + 2 <= e1; e += 2) {
        int src0 = __ldg(&g_esrc[e]);
        int src1 = __ldg(&g_esrc[e + 1]);
        uint2 kw0 = kv2[(long)src0 * 64 + lane];
        uint2 kw1 = kv2[(long)src1 * 64 + lane];
        uint2 vw0 = kv2[(long)src0 * 64 + 32 + lane];
        uint2 vw1 = kv2[(long)src1 * 64 + 32 + lane];
        float2 k0a = __bfloat1622float2(*reinterpret_cast<__nv_bfloat162*>(&kw0.x));
        float2 k0b = __bfloat1622float2(*reinterpret_cast<__nv_bfloat162*>(&kw0.y));
        float2 k1a = __bfloat1622float2(*reinterpret_cast<__nv_bfloat162*>(&kw1.x));
        float2 k1b = __bfloat1622float2(*reinterpret_cast<__nv_bfloat162*>(&kw1.y));
        float2 v0a = __half22float2(*reinterpret_cast<__half2*>(&vw0.x));
        float2 v0b = __half22float2(*reinterpret_cast<__half2*>(&vw0.y));
        float2 v1a = __half22float2(*reinterpret_cast<__half2*>(&vw1.x));
        float2 v1b = __half22float2(*reinterpret_cast<__half2*>(&vw1.y));
        float p0 = ql.x * k0a.x + ql.y * k0a.y + ql.z * k0b.x + ql.w * k0b.y;
        float p1 = ql.x * k1a.x + ql.y * k1a.y + ql.z * k1b.x + ql.w * k1b.y;
        p0 += __shfl_xor_sync(0xffffffffu, p0, 1);
        p1 += __shfl_xor_sync(0xffffffffu, p1, 1);
        p0 += __shfl_xor_sync(0xffffffffu, p0, 2);
        p1 += __shfl_xor_sync(0xffffffffu, p1, 2);
        p0 += __shfl_xor_sync(0xffffffffu, p0, 4);
        p1 += __shfl_xor_sync(0xffffffffu, p1, 4);
        float w0 = __expf(p0 * scale);
        float w1 = __expf(p1 * scale);
        s0 += w0; s1 += w1;
        a0.x += w0 * v0a.x; a0.y += w0 * v0a.y; a0.z += w0 * v0b.x; a0.w += w0 * v0b.y;
        a1.x += w1 * v1a.x; a1.y += w1 * v1a.y; a1.z += w1 * v1b.x; a1.w += w1 * v1b.y;
    }
    if (e < e1) {
        int src0 = __ldg(&g_esrc[e]);
        uint2 kw0 = kv2[(long)src0 * 64 + lane];
        uint2 vw0 = kv2[(long)src0 * 64 + 32 + lane];
        float2 k0a = __bfloat1622float2(*reinterpret_cast<__nv_bfloat162*>(&kw0.x));
        float2 k0b = __bfloat1622float2(*reinterpret_cast<__nv_bfloat162*>(&kw0.y));
        float2 v0a = __half22float2(*reinterpret_cast<__half2*>(&vw0.x));
        float2 v0b = __half22float2(*reinterpret_cast<__half2*>(&vw0.y));
        float p0 = ql.x * k0a.x + ql.y * k0a.y + ql.z * k0b.x + ql.w * k0b.y;
        p0 += __shfl_xor_sync(0xffffffffu, p0, 1);
        p0 += __shfl_xor_sync(0xffffffffu, p0, 2);
        p0 += __shfl_xor_sync(0xffffffffu, p0, 4);
        float w0 = __expf(p0 * scale);
        s0 += w0;
        a0.x += w0 * v0a.x; a0.y += w0 * v0a.y; a0.z += w0 * v0b.x; a0.w += w0 * v0b.y;
    }
    float s = s0 + s1;
    float inv = (s > 0.f) ? (1.f / s) : 0.f;
    float4 sk = qs4[(long)n * 64 + 32 + lane];
    float4 o;
    o.x = (a0.x + a1.x) * inv + sk.x;
    o.y = (a0.y + a1.y) * inv + sk.y;
    o.z = (a0.z + a1.z) * inv + sk.z;
    o.w = (a0.w + a1.w) * inv + sk.w;
    ((float4*)g_h1f)[(long)n * 32 + lane] = o;
}

// ---------------- host ----------------
extern "C" void kernel_launch(void* const* d_in, const int* in_sizes, int n_in,
                              void* d_out, int out_size)
{
    const float* x    = (const float*)d_in[0];
    const int*   ei   = (const int*)  d_in[1];
    const float* pW1  = (const float*)d_in[2];
    const float* pb1  = (const float*)d_in[3];
    const float* pW2  = (const float*)d_in[4];
    const float* pb2  = (const float*)d_in[5];
    const float* pW3  = (const float*)d_in[6];
    const float* pb3  = (const float*)d_in[7];
    const float* uW1  = (const float*)d_in[8];
    const float* ub1  = (const float*)d_in[9];
    const float* uW2  = (const float*)d_in[10];
    const float* ub2  = (const float*)d_in[11];
    const float* uW3  = (const float*)d_in[12];
    const float* ub3  = (const float*)d_in[13];
    const float* qW   = (const float*)d_in[14];
    const float* qb   = (const float*)d_in[15];
    const float* kW   = (const float*)d_in[16];
    const float* kb   = (const float*)d_in[17];
    const float* vW   = (const float*)d_in[18];
    const float* vb   = (const float*)d_in[19];
    const float* sW   = (const float*)d_in[20];
    const float* sb   = (const float*)d_in[21];
    float* out = (float*)d_out;

    const int F = 5;
    const int N = in_sizes[0] / F;
    const int E = in_sizes[1] / 2;
    const int* src = ei;
    const int* dst = ei + E;

    __nv_bfloat16 *h0h, *wh;
    uint32_t *kv;
    float *qs, *bc, *h0f, *h1f, *wf;
    cudaGetSymbolAddress((void**)&h0h, g_h0h);
    cudaGetSymbolAddress((void**)&h0f, g_h0f);
    cudaGetSymbolAddress((void**)&h1f, g_h1f);
    cudaGetSymbolAddress((void**)&qs,  g_qs);
    cudaGetSymbolAddress((void**)&kv,  g_kv);
    cudaGetSymbolAddress((void**)&bc,  g_bcat);
    cudaGetSymbolAddress((void**)&wh,  g_wth);
    cudaGetSymbolAddress((void**)&wf,  g_wtf);

    // ---- fork CSR build onto side stream ----
    cudaEventRecord(g_ev_fork, 0);
    cudaStreamWaitEvent(g_s2, g_ev_fork, 0);
    {
        int nb1024 = (N + 1023) / 1024;
        zero_cnt_kernel<<<(N + 255) / 256, 256, 0, g_s2>>>(N);
        hist_kernel<<<(E + 255) / 256, 256, 0, g_s2>>>(dst, E);
        scan1_kernel<<<nb1024, 1024, 0, g_s2>>>(N);
        scan2_kernel<<<1, 32, 0, g_s2>>>(nb1024);
        scan3_kernel<<<(N + 255) / 256, 256, 0, g_s2>>>(N, E);
        scatter_kernel<<<(E + 255) / 256, 256, 0, g_s2>>>(src, dst, E);
    }

    // ---- main chain ----
    {
        dim3 tgrid(4, 4, 9), tblk(32, 8);
        transpose_all<<<tgrid, tblk>>>(pW2, pW3, qW, kW, sW, vW, uW1, uW2, uW3);
        concat_bias<<<1, 512>>>(qb, kb, sb, vb);
    }
    {
        int smem = (38400 + 768) * 4;
        cudaFuncSetAttribute(fused_prep, cudaFuncAttributeMaxDynamicSharedMemorySize, smem);
        fused_prep<<<148, 512, smem>>>(x, pW1, pb1,
            wf + 0 * 16384, wf + 1 * 16384, pb2, pb3, h0h, h0f, N);
    }
    cudaEventRecord(g_ev_prep, 0);

    // qk (bf16 1-term) on side stream
    cudaStreamWaitEvent(g_s2, g_ev_prep, 0);
    {
        int smemA = (256 * 136 + 64 * 136) * 2;
        cudaFuncSetAttribute(gemm_qk, cudaFuncAttributeMaxDynamicSharedMemorySize, smemA);
        gemm_qk<<<148, 512, smemA, g_s2>>>(h0h, wh + 2 * 16384, bc, qs, kv, N);
        cudaEventRecord(g_ev_join, g_s2);
    }
    {
        int smemB = (256 * 132 + 64 * 132) * 4;
        cudaFuncSetAttribute(gemm_sv_t32, cudaFuncAttributeMaxDynamicSharedMemorySize, smemB);
        gemm_sv_t32<<<148, 512, smemB>>>(h0f, wf + 2 * 16384, bc + 256, qs, kv, N);
    }

    cudaStreamWaitEvent(0, g_ev_join, 0);

    long tt = (long)N * 32;
    attn_kernel<<<(int)((tt + 255) / 256), 256>>>(N);

    {
        int smem = 55296 * 4;
        cudaFuncSetAttribute(fused_update_t32, cudaFuncAttributeMaxDynamicSharedMemorySize, smem);
        fused_update_t32<<<148, 512, smem>>>(h1f,
            wf + 4 * 16384, wf + 5 * 16384, wf + 6 * 16384,
            ub1, ub2, ub3, out, N);
    }
}